// round 2
// baseline (speedup 1.0000x reference)
#include <cuda_runtime.h>
#include <math.h>

#define BB 2
#define S_IMG 1024
#define S_TXT 512
#define SEQ 1536
#define DIM 3072
#define HEADS 24
#define HD 128
#define EPSF 1e-6f
#define SCALEF 0.08838834764831845f

// Scratch (device globals -- no allocation allowed)
__device__ float g_QJ[BB * SEQ * DIM];
__device__ float g_KJ[BB * SEQ * DIM];
__device__ float g_VJ[BB * SEQ * DIM];
__device__ float g_AO[BB * SEQ * DIM];

// ---------------------------------------------------------------------------
// SGEMM: C[r][n] = sum_k A[r][k] * W[k][n] + bias[n]
// Tile: 128x128, K-step 8, 256 threads, 8x8 per-thread microtile.
// ---------------------------------------------------------------------------
__global__ void __launch_bounds__(256) sgemm_kernel(
    const float* __restrict__ A_base, int a_seq, int a_off, int rpb,
    const float* __restrict__ W, const float* __restrict__ bias,
    float* __restrict__ C_base, int c_seq, int c_off)
{
    __shared__ __align__(16) float As[8][128];
    __shared__ __align__(16) float Bs[8][128];
    const int tid  = threadIdx.x;
    const int row0 = blockIdx.y * 128;
    const int col0 = blockIdx.x * 128;
    const int b    = row0 / rpb;      // tiles never straddle batches (rpb % 128 == 0)
    const int s0   = row0 % rpb;
    const float* A = A_base + ((size_t)(b * a_seq + a_off + s0)) * DIM;
    float*       C = C_base + ((size_t)(b * c_seq + c_off + s0)) * DIM;

    const int am = tid >> 1;          // A tile row (0..127)
    const int ak = (tid & 1) * 4;     // A tile k (0 or 4)
    const int bk = tid >> 5;          // B tile k row (0..7)
    const int bn = (tid & 31) * 4;    // B tile col
    const int tm = (tid >> 4) * 8;
    const int tn = (tid & 15) * 8;

    float acc[8][8];
#pragma unroll
    for (int i = 0; i < 8; i++)
#pragma unroll
        for (int j = 0; j < 8; j++) acc[i][j] = 0.f;

    for (int k0 = 0; k0 < DIM; k0 += 8) {
        float4 av = *(const float4*)(A + (size_t)am * DIM + k0 + ak);
        float4 bv = *(const float4*)(W + (size_t)(k0 + bk) * DIM + col0 + bn);
        As[ak + 0][am] = av.x; As[ak + 1][am] = av.y;
        As[ak + 2][am] = av.z; As[ak + 3][am] = av.w;
        *(float4*)&Bs[bk][bn] = bv;
        __syncthreads();
#pragma unroll
        for (int kk = 0; kk < 8; kk++) {
            float4 a0 = *(const float4*)&As[kk][tm];
            float4 a1 = *(const float4*)&As[kk][tm + 4];
            float4 b0 = *(const float4*)&Bs[kk][tn];
            float4 b1 = *(const float4*)&Bs[kk][tn + 4];
            float ar[8] = {a0.x, a0.y, a0.z, a0.w, a1.x, a1.y, a1.z, a1.w};
            float br[8] = {b0.x, b0.y, b0.z, b0.w, b1.x, b1.y, b1.z, b1.w};
#pragma unroll
            for (int i = 0; i < 8; i++)
#pragma unroll
                for (int j = 0; j < 8; j++) acc[i][j] += ar[i] * br[j];
        }
        __syncthreads();
    }
#pragma unroll
    for (int i = 0; i < 8; i++) {
        float* crow = C + (size_t)(tm + i) * DIM + col0;
#pragma unroll
        for (int j = 0; j < 8; j++) crow[tn + j] = acc[i][j] + bias[col0 + tn + j];
    }
}

// ---------------------------------------------------------------------------
// Fused RMS-norm (per head-vector of 128) + RoPE for Q and K joint tensors.
// One block = one (b, s, h). txt rows (s < S_TXT) use g_qc/g_kc.
// ---------------------------------------------------------------------------
__global__ void __launch_bounds__(128) rmsrope_kernel(
    float* __restrict__ Q, float* __restrict__ K,
    const float* __restrict__ cosb, const float* __restrict__ sinb,
    const float* __restrict__ gq, const float* __restrict__ gk,
    const float* __restrict__ gqc, const float* __restrict__ gkc)
{
    const int idx = blockIdx.x;
    const int h = idx % HEADS;
    const int s = (idx / HEADS) % SEQ;
    const int b = idx / (HEADS * SEQ);
    const int d = threadIdx.x;
    const size_t off = ((size_t)(b * SEQ + s)) * DIM + h * HD + d;
    __shared__ float sh[HD];
    __shared__ float red[4];
    const float c  = cosb[s * (HD / 2) + (d >> 1)];
    const float sn = sinb[s * (HD / 2) + (d >> 1)];
    const bool txt = (s < S_TXT);

    // ---- Q ----
    {
        float v = Q[off];
        float sq = v * v;
#pragma unroll
        for (int o = 16; o > 0; o >>= 1) sq += __shfl_xor_sync(0xffffffffu, sq, o);
        if ((d & 31) == 0) red[d >> 5] = sq;
        __syncthreads();
        float mean = (red[0] + red[1] + red[2] + red[3]) * (1.0f / HD);
        float scl = rsqrtf(mean + EPSF) * (txt ? gqc[d] : gq[d]);
        sh[d] = v * scl;
        __syncthreads();
        float out = ((d & 1) == 0) ? (sh[d] * c - sh[d + 1] * sn)
                                   : (sh[d - 1] * sn + sh[d] * c);
        Q[off] = out;
    }
    __syncthreads();
    // ---- K ----
    {
        float v = K[off];
        float sq = v * v;
#pragma unroll
        for (int o = 16; o > 0; o >>= 1) sq += __shfl_xor_sync(0xffffffffu, sq, o);
        if ((d & 31) == 0) red[d >> 5] = sq;
        __syncthreads();
        float mean = (red[0] + red[1] + red[2] + red[3]) * (1.0f / HD);
        float scl = rsqrtf(mean + EPSF) * (txt ? gkc[d] : gk[d]);
        sh[d] = v * scl;
        __syncthreads();
        float out = ((d & 1) == 0) ? (sh[d] * c - sh[d + 1] * sn)
                                   : (sh[d - 1] * sn + sh[d] * c);
        K[off] = out;
    }
}

// ---------------------------------------------------------------------------
// Flash attention fp32. One block per (q-tile of 64 rows, b*h).
// BM=64, BN=32, HD=128. 256 threads, 8 warps; warp w owns output rows 8w..8w+7.
// Dynamic smem: Qs 64x129 | KV (K: 32x129 / V: 32x128 union) | Ss 64x33.
// Stride 129 => K-tile row base advances 1 bank per row; the 16 distinct even
// rows read in the score phase map to 16 distinct banks (conflict-free).
// ---------------------------------------------------------------------------
#define FBM 64
#define FBN 32
#define QS_ST 129
#define KS_ST 129
#define QS_ELEMS (FBM * QS_ST)                 // 8256
#define KV_ELEMS (FBN * KS_ST)                 // 4128 (>= 32*128 V tile)
#define SS_ELEMS (FBM * 33)                    // 2112
#define FLASH_SMEM_BYTES ((QS_ELEMS + KV_ELEMS + SS_ELEMS) * 4)  // 57984

__global__ void __launch_bounds__(256) flash_kernel(
    const float* __restrict__ Q, const float* __restrict__ K,
    const float* __restrict__ V, float* __restrict__ O)
{
    extern __shared__ __align__(16) float smem[];
    float* Qs = smem;                          // [FBM][QS_ST]
    float* KV = smem + QS_ELEMS;               // K: [FBN][KS_ST] / V: [FBN][128]
    float* Ss = smem + QS_ELEMS + KV_ELEMS;    // [FBM][33]

    const int tid = threadIdx.x;
    const int warp = tid >> 5, lane = tid & 31;
    const int qt = blockIdx.x;
    const int bh = blockIdx.y;
    const int b = bh / HEADS, h = bh % HEADS;
    const int q0 = qt * FBM;
    const float* Qg = Q + ((size_t)b * SEQ) * DIM + h * HD;
    const float* Kg = K + ((size_t)b * SEQ) * DIM + h * HD;
    const float* Vg = V + ((size_t)b * SEQ) * DIM + h * HD;

    // Load Q tile
    for (int i = tid; i < FBM * 32; i += 256) {
        int r = i >> 5, d4 = (i & 31) << 2;
        float4 v = *(const float4*)(Qg + (size_t)(q0 + r) * DIM + d4);
        Qs[r * QS_ST + d4 + 0] = v.x; Qs[r * QS_ST + d4 + 1] = v.y;
        Qs[r * QS_ST + d4 + 2] = v.z; Qs[r * QS_ST + d4 + 3] = v.w;
    }

    const int sr = (tid >> 4) << 2;   // score microtile: 4 rows
    const int sc = (tid & 15) << 1;   //                  2 cols

    float acc[8][4];
#pragma unroll
    for (int r = 0; r < 8; r++) { acc[r][0] = acc[r][1] = acc[r][2] = acc[r][3] = 0.f; }
    float m_i[8], l_i[8];
#pragma unroll
    for (int r = 0; r < 8; r++) { m_i[r] = -1e30f; l_i[r] = 0.f; }

    for (int kt = 0; kt < SEQ / FBN; kt++) {
        const int k0 = kt * FBN;
        __syncthreads();
        // K tile -> KV (stride KS_ST)
        for (int i = tid; i < FBN * 32; i += 256) {
            int r = i >> 5, d4 = (i & 31) << 2;
            float4 v = *(const float4*)(Kg + (size_t)(k0 + r) * DIM + d4);
            KV[r * KS_ST + d4 + 0] = v.x; KV[r * KS_ST + d4 + 1] = v.y;
            KV[r * KS_ST + d4 + 2] = v.z; KV[r * KS_ST + d4 + 3] = v.w;
        }
        __syncthreads();
        // Scores: S = Q K^T * SCALE
        float sacc[4][2];
#pragma unroll
        for (int i = 0; i < 4; i++) { sacc[i][0] = 0.f; sacc[i][1] = 0.f; }
#pragma unroll 4
        for (int d = 0; d < HD; d++) {
            float a0 = Qs[(sr + 0) * QS_ST + d];
            float a1 = Qs[(sr + 1) * QS_ST + d];
            float a2 = Qs[(sr + 2) * QS_ST + d];
            float a3 = Qs[(sr + 3) * QS_ST + d];
            float b0 = KV[(sc + 0) * KS_ST + d];
            float b1 = KV[(sc + 1) * KS_ST + d];
            sacc[0][0] += a0 * b0; sacc[0][1] += a0 * b1;
            sacc[1][0] += a1 * b0; sacc[1][1] += a1 * b1;
            sacc[2][0] += a2 * b0; sacc[2][1] += a2 * b1;
            sacc[3][0] += a3 * b0; sacc[3][1] += a3 * b1;
        }
#pragma unroll
        for (int i = 0; i < 4; i++) {
            Ss[(sr + i) * 33 + sc + 0] = sacc[i][0] * SCALEF;
            Ss[(sr + i) * 33 + sc + 1] = sacc[i][1] * SCALEF;
        }
        __syncthreads();
        // Online softmax: warp w handles rows 8w..8w+7, lane = column (BN=32)
#pragma unroll
        for (int r = 0; r < 8; r++) {
            int R = warp * 8 + r;
            float s1 = Ss[R * 33 + lane];
            float mx = s1;
#pragma unroll
            for (int o = 16; o > 0; o >>= 1) mx = fmaxf(mx, __shfl_xor_sync(0xffffffffu, mx, o));
            float mn = fmaxf(m_i[r], mx);
            float f  = __expf(m_i[r] - mn);
            float p1 = __expf(s1 - mn);
            Ss[R * 33 + lane] = p1;
            float rs = p1;
#pragma unroll
            for (int o = 16; o > 0; o >>= 1) rs += __shfl_xor_sync(0xffffffffu, rs, o);
            l_i[r] = l_i[r] * f + rs;
            m_i[r] = mn;
            acc[r][0] *= f; acc[r][1] *= f; acc[r][2] *= f; acc[r][3] *= f;
        }
        __syncthreads();
        // V tile -> KV (stride 128, float4)
        for (int i = tid; i < FBN * 32; i += 256) {
            int r = i >> 5, d4 = (i & 31) << 2;
            float4 v = *(const float4*)(Vg + (size_t)(k0 + r) * DIM + d4);
            *(float4*)&KV[r * 128 + d4] = v;
        }
        __syncthreads();
        // O += P @ V
#pragma unroll 2
        for (int kk = 0; kk < FBN; kk++) {
            float4 vv = *(const float4*)&KV[kk * 128 + lane * 4];
#pragma unroll
            for (int r = 0; r < 8; r++) {
                float p = Ss[(warp * 8 + r) * 33 + kk];
                acc[r][0] += p * vv.x; acc[r][1] += p * vv.y;
                acc[r][2] += p * vv.z; acc[r][3] += p * vv.w;
            }
        }
    }
    // Epilogue: normalize by l and store
#pragma unroll
    for (int r = 0; r < 8; r++) {
        int R = q0 + warp * 8 + r;
        float inv = 1.0f / l_i[r];
        float4 o4 = make_float4(acc[r][0] * inv, acc[r][1] * inv,
                                acc[r][2] * inv, acc[r][3] * inv);
        *(float4*)(O + ((size_t)(b * SEQ + R)) * DIM + h * HD + lane * 4) = o4;
    }
}

// ---------------------------------------------------------------------------
extern "C" void kernel_launch(void* const* d_in, const int* in_sizes, int n_in,
                              void* d_out, int out_size)
{
    (void)in_sizes; (void)n_in; (void)out_size;
    const float* x     = (const float*)d_in[0];
    const float* ctx   = (const float*)d_in[1];
    const float* cosb  = (const float*)d_in[2];
    const float* sinb  = (const float*)d_in[3];
    const float* wq    = (const float*)d_in[4];
    const float* bq    = (const float*)d_in[5];
    const float* wk    = (const float*)d_in[6];
    const float* bk    = (const float*)d_in[7];
    const float* wv    = (const float*)d_in[8];
    const float* bv    = (const float*)d_in[9];
    const float* wqc   = (const float*)d_in[10];
    const float* bqc   = (const float*)d_in[11];
    const float* wkc   = (const float*)d_in[12];
    const float* bkc   = (const float*)d_in[13];
    const float* wvc   = (const float*)d_in[14];
    const float* bvc   = (const float*)d_in[15];
    const float* w_out = (const float*)d_in[16];
    const float* b_out = (const float*)d_in[17];
    const float* w_add = (const float*)d_in[18];
    const float* b_add = (const float*)d_in[19];
    const float* g_q   = (const float*)d_in[20];
    const float* g_k   = (const float*)d_in[21];
    const float* g_qc  = (const float*)d_in[22];
    const float* g_kc  = (const float*)d_in[23];
    float* out = (float*)d_out;

    float *QJ, *KJ, *VJ, *AO;
    cudaGetSymbolAddress((void**)&QJ, g_QJ);
    cudaGetSymbolAddress((void**)&KJ, g_KJ);
    cudaGetSymbolAddress((void**)&VJ, g_VJ);
    cudaGetSymbolAddress((void**)&AO, g_AO);

    static int smem_set = 0;
    if (!smem_set) {
        cudaFuncSetAttribute(flash_kernel,
                             cudaFuncAttributeMaxDynamicSharedMemorySize,
                             FLASH_SMEM_BYTES);
        smem_set = 1;
    }

    dim3 gImg(DIM / 128, (BB * S_IMG) / 128);   // (24, 16)
    dim3 gTxt(DIM / 128, (BB * S_TXT) / 128);   // (24, 8)

    // QKV projections (img rows -> joint seq offset 512, txt rows -> offset 0)
    sgemm_kernel<<<gImg, 256>>>(x,   S_IMG, 0, S_IMG, wq,  bq,  QJ, SEQ, S_TXT);
    sgemm_kernel<<<gTxt, 256>>>(ctx, S_TXT, 0, S_TXT, wqc, bqc, QJ, SEQ, 0);
    sgemm_kernel<<<gImg, 256>>>(x,   S_IMG, 0, S_IMG, wk,  bk,  KJ, SEQ, S_TXT);
    sgemm_kernel<<<gTxt, 256>>>(ctx, S_TXT, 0, S_TXT, wkc, bkc, KJ, SEQ, 0);
    sgemm_kernel<<<gImg, 256>>>(x,   S_IMG, 0, S_IMG, wv,  bv,  VJ, SEQ, S_TXT);
    sgemm_kernel<<<gTxt, 256>>>(ctx, S_TXT, 0, S_TXT, wvc, bvc, VJ, SEQ, 0);

    // RMS-norm + RoPE on Q and K (joint positions)
    rmsrope_kernel<<<BB * SEQ * HEADS, 128>>>(QJ, KJ, cosb, sinb, g_q, g_k, g_qc, g_kc);

    // Attention
    flash_kernel<<<dim3(SEQ / FBM, BB * HEADS), 256, FLASH_SMEM_BYTES>>>(QJ, KJ, VJ, AO);

    // Output projections: txt (rows 0..511 of each batch) then img
    sgemm_kernel<<<gTxt, 256>>>(AO, SEQ, 0,     S_TXT, w_add, b_add, out, S_TXT, 0);
    sgemm_kernel<<<gImg, 256>>>(AO, SEQ, S_TXT, S_IMG, w_out, b_out,
                                out + (size_t)BB * S_TXT * DIM, S_IMG, 0);
}

// round 4
// speedup vs baseline: 1.7166x; 1.7166x over previous
#include <cuda_runtime.h>
#include <cuda_bf16.h>
#include <cstdint>
#include <math.h>

#define BB 2
#define S_IMG 1024
#define S_TXT 512
#define SEQ 1536
#define DIM 3072
#define HEADS 24
#define HD 128
#define EPSF 1e-6f
#define SCALEF 0.08838834764831845f

// Scratch (device globals -- no allocation allowed)
__device__ float g_QJ[BB * SEQ * DIM];
__device__ float g_KJ[BB * SEQ * DIM];
__device__ float g_VJ[BB * SEQ * DIM];
__device__ float g_AO[BB * SEQ * DIM];

// ===========================================================================
// mma.sync helpers (baseline sm_80+ ISA -- harness emits compute_103 PTX,
// so arch-specific 'a' features (tcgen05 etc.) are unavailable)
// ===========================================================================
__device__ __forceinline__ uint32_t smem_u32(const void* p) {
    uint32_t a;
    asm("{ .reg .u64 t; cvta.to.shared.u64 t, %1; cvt.u32.u64 %0, t; }"
        : "=r"(a) : "l"(p));
    return a;
}
#define LDM4(r, a) \
    asm volatile("ldmatrix.sync.aligned.m8n8.x4.shared.b16 {%0,%1,%2,%3}, [%4];" \
        : "=r"((r)[0]), "=r"((r)[1]), "=r"((r)[2]), "=r"((r)[3]) : "r"(a))
#define LDM4T(r, a) \
    asm volatile("ldmatrix.sync.aligned.m8n8.x4.trans.shared.b16 {%0,%1,%2,%3}, [%4];" \
        : "=r"((r)[0]), "=r"((r)[1]), "=r"((r)[2]), "=r"((r)[3]) : "r"(a))
#define MMA_BF16(d, a, b0, b1) \
    asm volatile("mma.sync.aligned.m16n8k16.row.col.f32.bf16.bf16.f32 " \
        "{%0,%1,%2,%3}, {%4,%5,%6,%7}, {%8,%9}, {%0,%1,%2,%3};" \
        : "+f"((d)[0]), "+f"((d)[1]), "+f"((d)[2]), "+f"((d)[3]) \
        : "r"((a)[0]), "r"((a)[1]), "r"((a)[2]), "r"((a)[3]), "r"(b0), "r"(b1))

__device__ __forceinline__ void split_bf16x4(float4 v, uint2& ph, uint2& pl) {
    __nv_bfloat16 h0 = __float2bfloat16(v.x);
    __nv_bfloat16 h1 = __float2bfloat16(v.y);
    __nv_bfloat16 h2 = __float2bfloat16(v.z);
    __nv_bfloat16 h3 = __float2bfloat16(v.w);
    __nv_bfloat16 l0 = __float2bfloat16(v.x - __bfloat162float(h0));
    __nv_bfloat16 l1 = __float2bfloat16(v.y - __bfloat162float(h1));
    __nv_bfloat16 l2 = __float2bfloat16(v.z - __bfloat162float(h2));
    __nv_bfloat16 l3 = __float2bfloat16(v.w - __bfloat162float(h3));
    ph.x = ((uint32_t)__bfloat16_as_ushort(h1) << 16) | __bfloat16_as_ushort(h0);
    ph.y = ((uint32_t)__bfloat16_as_ushort(h3) << 16) | __bfloat16_as_ushort(h2);
    pl.x = ((uint32_t)__bfloat16_as_ushort(l1) << 16) | __bfloat16_as_ushort(l0);
    pl.y = ((uint32_t)__bfloat16_as_ushort(l3) << 16) | __bfloat16_as_ushort(l2);
}

// ===========================================================================
// bf16-split GEMM via mma.sync: C[128x128] = A[128x3072] @ W[3072x128] + bias
// 3 passes: Ahi*Bhi + Ahi*Blo + Alo*Bhi (fp32 accum). KC=32, double-buffered.
// A smem rows padded to 40 bf16 (80B), B rows to 136 bf16 (272B): ldmatrix
// phases hit 8 distinct 16B slots -> conflict-free.
// ===========================================================================
#define KC 32
#define CHUNKS (DIM / KC)                 // 96
#define A_ST2 80                           // bytes per A smem row
#define B_ST2 272                          // bytes per B smem row
#define A_TILE_B (128 * A_ST2)             // 10240
#define B_TILE_B (32 * B_ST2)              // 8704
#define OFF_AHI 0
#define OFF_ALO A_TILE_B
#define OFF_BHI (2 * A_TILE_B)
#define OFF_BLO (2 * A_TILE_B + B_TILE_B)
#define STAGE_B (2 * A_TILE_B + 2 * B_TILE_B)   // 37888
#define GEMM_SMEM_BYTES (2 * STAGE_B)           // 75776

__global__ void __launch_bounds__(256) mma_gemm_kernel(
    const float* __restrict__ A_base, int a_seq, int a_off, int rpb,
    const float* __restrict__ W, const float* __restrict__ bias,
    float* __restrict__ C_base, int c_seq, int c_off)
{
    extern __shared__ __align__(128) char smem[];
    const uint32_t sbase = smem_u32(smem);
    const int tid = threadIdx.x;
    const int wid = tid >> 5, lane = tid & 31;
    const int warp_m = wid & 3;            // 4 warps over M (32 rows each)
    const int warp_n = wid >> 2;           // 2 warps over N (64 cols each)

    const int row0 = blockIdx.y * 128;
    const int col0 = blockIdx.x * 128;
    const int b  = row0 / rpb;             // rpb % 128 == 0
    const int s0 = row0 % rpb;
    const float* A = A_base + (size_t)(b * a_seq + a_off + s0) * DIM;
    float*       C = C_base + (size_t)(b * c_seq + c_off + s0) * DIM;

    float acc[2][8][4];
#pragma unroll
    for (int i = 0; i < 2; i++)
#pragma unroll
        for (int j = 0; j < 8; j++)
#pragma unroll
            for (int k = 0; k < 4; k++) acc[i][j][k] = 0.f;

    float4 rA[4], rB[4];

#define LOADG(c) do { \
    const int k0 = (c) * KC; \
    _Pragma("unroll") \
    for (int i = 0; i < 4; i++) { \
        int f = tid + i * 256; \
        rA[i] = *(const float4*)(A + (size_t)(f >> 3) * DIM + k0 + ((f & 7) << 2)); \
        rB[i] = *(const float4*)(W + (size_t)(k0 + (f >> 5)) * DIM + col0 + ((f & 31) << 2)); \
    } \
} while (0)

#define STORES(s) do { \
    char* st = smem + (s) * STAGE_B; \
    _Pragma("unroll") \
    for (int i = 0; i < 4; i++) { \
        int f = tid + i * 256; \
        uint2 ph, pl; \
        split_bf16x4(rA[i], ph, pl); \
        uint32_t offa = (uint32_t)(f >> 3) * A_ST2 + ((f & 7) << 3); \
        *(uint2*)(st + OFF_AHI + offa) = ph; \
        *(uint2*)(st + OFF_ALO + offa) = pl; \
        split_bf16x4(rB[i], ph, pl); \
        uint32_t offb = (uint32_t)(f >> 5) * B_ST2 + ((f & 31) << 3); \
        *(uint2*)(st + OFF_BHI + offb) = ph; \
        *(uint2*)(st + OFF_BLO + offb) = pl; \
    } \
} while (0)

    const uint32_t a_row  = (uint32_t)(warp_m * 32 + (lane & 15));
    const uint32_t a_col8 = (uint32_t)(((lane >> 4) << 3) * 2);
    const uint32_t b_row  = (uint32_t)(lane & 15);
    const uint32_t b_col8 = (uint32_t)((warp_n * 64 + ((lane >> 4) << 3)) * 2);

#define COMPUTE(s) do { \
    const uint32_t sb = sbase + (s) * STAGE_B; \
    _Pragma("unroll") \
    for (int ks = 0; ks < 2; ks++) { \
        uint32_t ah[2][4], al[2][4]; \
        _Pragma("unroll") \
        for (int mt = 0; mt < 2; mt++) { \
            uint32_t ad = sb + OFF_AHI + (a_row + mt * 16) * A_ST2 + ks * 32 + a_col8; \
            LDM4(ah[mt], ad); \
            LDM4(al[mt], ad + A_TILE_B); \
        } \
        _Pragma("unroll") \
        for (int ng = 0; ng < 4; ng++) { \
            uint32_t bh[4], bl[4]; \
            uint32_t bd = sb + OFF_BHI + (ks * 16 + b_row) * B_ST2 + b_col8 + ng * 32; \
            LDM4T(bh, bd); \
            LDM4T(bl, bd + B_TILE_B); \
            _Pragma("unroll") \
            for (int mt = 0; mt < 2; mt++) { \
                MMA_BF16(acc[mt][ng * 2 + 0], ah[mt], bh[0], bh[1]); \
                MMA_BF16(acc[mt][ng * 2 + 0], ah[mt], bl[0], bl[1]); \
                MMA_BF16(acc[mt][ng * 2 + 0], al[mt], bh[0], bh[1]); \
                MMA_BF16(acc[mt][ng * 2 + 1], ah[mt], bh[2], bh[3]); \
                MMA_BF16(acc[mt][ng * 2 + 1], ah[mt], bl[2], bl[3]); \
                MMA_BF16(acc[mt][ng * 2 + 1], al[mt], bh[2], bh[3]); \
            } \
        } \
    } \
} while (0)

    // prologue
    LOADG(0);
    STORES(0);
    __syncthreads();
    for (int c = 0; c < CHUNKS; c++) {
        if (c + 1 < CHUNKS) LOADG(c + 1);
        COMPUTE(c & 1);
        __syncthreads();
        if (c + 1 < CHUNKS) STORES((c + 1) & 1);
        __syncthreads();
    }

    // epilogue: d frag -> lane (l>>2) = row, (l&3)*2 = col pair; +8 rows for d2,d3
    const int m_base = warp_m * 32;
    const int n_base = col0 + warp_n * 64;
#pragma unroll
    for (int mt = 0; mt < 2; mt++) {
#pragma unroll
        for (int nt = 0; nt < 8; nt++) {
            int r  = m_base + mt * 16 + (lane >> 2);
            int cc = n_base + nt * 8 + ((lane & 3) << 1);
            float b0 = bias[cc], b1 = bias[cc + 1];
            float2 v0 = make_float2(acc[mt][nt][0] + b0, acc[mt][nt][1] + b1);
            float2 v1 = make_float2(acc[mt][nt][2] + b0, acc[mt][nt][3] + b1);
            *(float2*)(C + (size_t)r * DIM + cc) = v0;
            *(float2*)(C + (size_t)(r + 8) * DIM + cc) = v1;
        }
    }
#undef LOADG
#undef STORES
#undef COMPUTE
}

// ---------------------------------------------------------------------------
// Fused RMS-norm (per head-vector of 128) + RoPE for Q and K joint tensors.
// ---------------------------------------------------------------------------
__global__ void __launch_bounds__(128) rmsrope_kernel(
    float* __restrict__ Q, float* __restrict__ K,
    const float* __restrict__ cosb, const float* __restrict__ sinb,
    const float* __restrict__ gq, const float* __restrict__ gk,
    const float* __restrict__ gqc, const float* __restrict__ gkc)
{
    const int idx = blockIdx.x;
    const int h = idx % HEADS;
    const int s = (idx / HEADS) % SEQ;
    const int b = idx / (HEADS * SEQ);
    const int d = threadIdx.x;
    const size_t off = ((size_t)(b * SEQ + s)) * DIM + h * HD + d;
    __shared__ float sh[HD];
    __shared__ float red[4];
    const float c  = cosb[s * (HD / 2) + (d >> 1)];
    const float sn = sinb[s * (HD / 2) + (d >> 1)];
    const bool txt = (s < S_TXT);

    {
        float v = Q[off];
        float sq = v * v;
#pragma unroll
        for (int o = 16; o > 0; o >>= 1) sq += __shfl_xor_sync(0xffffffffu, sq, o);
        if ((d & 31) == 0) red[d >> 5] = sq;
        __syncthreads();
        float mean = (red[0] + red[1] + red[2] + red[3]) * (1.0f / HD);
        float scl = rsqrtf(mean + EPSF) * (txt ? gqc[d] : gq[d]);
        sh[d] = v * scl;
        __syncthreads();
        float out = ((d & 1) == 0) ? (sh[d] * c - sh[d + 1] * sn)
                                   : (sh[d - 1] * sn + sh[d] * c);
        Q[off] = out;
    }
    __syncthreads();
    {
        float v = K[off];
        float sq = v * v;
#pragma unroll
        for (int o = 16; o > 0; o >>= 1) sq += __shfl_xor_sync(0xffffffffu, sq, o);
        if ((d & 31) == 0) red[d >> 5] = sq;
        __syncthreads();
        float mean = (red[0] + red[1] + red[2] + red[3]) * (1.0f / HD);
        float scl = rsqrtf(mean + EPSF) * (txt ? gkc[d] : gk[d]);
        sh[d] = v * scl;
        __syncthreads();
        float out = ((d & 1) == 0) ? (sh[d] * c - sh[d + 1] * sn)
                                   : (sh[d - 1] * sn + sh[d] * c);
        K[off] = out;
    }
}

// ---------------------------------------------------------------------------
// Flash attention fp32 (unchanged from Round 2 pass).
// ---------------------------------------------------------------------------
#define FBM 64
#define FBN 32
#define QS_ST 129
#define KS_ST 129
#define QS_ELEMS (FBM * QS_ST)
#define KV_ELEMS (FBN * KS_ST)
#define SS_ELEMS (FBM * 33)
#define FLASH_SMEM_BYTES ((QS_ELEMS + KV_ELEMS + SS_ELEMS) * 4)

__global__ void __launch_bounds__(256) flash_kernel(
    const float* __restrict__ Q, const float* __restrict__ K,
    const float* __restrict__ V, float* __restrict__ O)
{
    extern __shared__ __align__(16) float fsm[];
    float* Qs = fsm;
    float* KV = fsm + QS_ELEMS;
    float* Ss = fsm + QS_ELEMS + KV_ELEMS;

    const int tid = threadIdx.x;
    const int warp = tid >> 5, lane = tid & 31;
    const int qt = blockIdx.x;
    const int bh = blockIdx.y;
    const int b = bh / HEADS, h = bh % HEADS;
    const int q0 = qt * FBM;
    const float* Qg = Q + ((size_t)b * SEQ) * DIM + h * HD;
    const float* Kg = K + ((size_t)b * SEQ) * DIM + h * HD;
    const float* Vg = V + ((size_t)b * SEQ) * DIM + h * HD;

    for (int i = tid; i < FBM * 32; i += 256) {
        int r = i >> 5, d4 = (i & 31) << 2;
        float4 v = *(const float4*)(Qg + (size_t)(q0 + r) * DIM + d4);
        Qs[r * QS_ST + d4 + 0] = v.x; Qs[r * QS_ST + d4 + 1] = v.y;
        Qs[r * QS_ST + d4 + 2] = v.z; Qs[r * QS_ST + d4 + 3] = v.w;
    }

    const int sr = (tid >> 4) << 2;
    const int sc = (tid & 15) << 1;

    float acc[8][4];
#pragma unroll
    for (int r = 0; r < 8; r++) { acc[r][0] = acc[r][1] = acc[r][2] = acc[r][3] = 0.f; }
    float m_i[8], l_i[8];
#pragma unroll
    for (int r = 0; r < 8; r++) { m_i[r] = -1e30f; l_i[r] = 0.f; }

    for (int kt = 0; kt < SEQ / FBN; kt++) {
        const int k0 = kt * FBN;
        __syncthreads();
        for (int i = tid; i < FBN * 32; i += 256) {
            int r = i >> 5, d4 = (i & 31) << 2;
            float4 v = *(const float4*)(Kg + (size_t)(k0 + r) * DIM + d4);
            KV[r * KS_ST + d4 + 0] = v.x; KV[r * KS_ST + d4 + 1] = v.y;
            KV[r * KS_ST + d4 + 2] = v.z; KV[r * KS_ST + d4 + 3] = v.w;
        }
        __syncthreads();
        float sacc[4][2];
#pragma unroll
        for (int i = 0; i < 4; i++) { sacc[i][0] = 0.f; sacc[i][1] = 0.f; }
#pragma unroll 4
        for (int d = 0; d < HD; d++) {
            float a0 = Qs[(sr + 0) * QS_ST + d];
            float a1 = Qs[(sr + 1) * QS_ST + d];
            float a2 = Qs[(sr + 2) * QS_ST + d];
            float a3 = Qs[(sr + 3) * QS_ST + d];
            float b0 = KV[(sc + 0) * KS_ST + d];
            float b1 = KV[(sc + 1) * KS_ST + d];
            sacc[0][0] += a0 * b0; sacc[0][1] += a0 * b1;
            sacc[1][0] += a1 * b0; sacc[1][1] += a1 * b1;
            sacc[2][0] += a2 * b0; sacc[2][1] += a2 * b1;
            sacc[3][0] += a3 * b0; sacc[3][1] += a3 * b1;
        }
#pragma unroll
        for (int i = 0; i < 4; i++) {
            Ss[(sr + i) * 33 + sc + 0] = sacc[i][0] * SCALEF;
            Ss[(sr + i) * 33 + sc + 1] = sacc[i][1] * SCALEF;
        }
        __syncthreads();
#pragma unroll
        for (int r = 0; r < 8; r++) {
            int R = warp * 8 + r;
            float s1 = Ss[R * 33 + lane];
            float mx = s1;
#pragma unroll
            for (int o = 16; o > 0; o >>= 1) mx = fmaxf(mx, __shfl_xor_sync(0xffffffffu, mx, o));
            float mn = fmaxf(m_i[r], mx);
            float f  = __expf(m_i[r] - mn);
            float p1 = __expf(s1 - mn);
            Ss[R * 33 + lane] = p1;
            float rs = p1;
#pragma unroll
            for (int o = 16; o > 0; o >>= 1) rs += __shfl_xor_sync(0xffffffffu, rs, o);
            l_i[r] = l_i[r] * f + rs;
            m_i[r] = mn;
            acc[r][0] *= f; acc[r][1] *= f; acc[r][2] *= f; acc[r][3] *= f;
        }
        __syncthreads();
        for (int i = tid; i < FBN * 32; i += 256) {
            int r = i >> 5, d4 = (i & 31) << 2;
            float4 v = *(const float4*)(Vg + (size_t)(k0 + r) * DIM + d4);
            *(float4*)&KV[r * 128 + d4] = v;
        }
        __syncthreads();
#pragma unroll 2
        for (int kk = 0; kk < FBN; kk++) {
            float4 vv = *(const float4*)&KV[kk * 128 + lane * 4];
#pragma unroll
            for (int r = 0; r < 8; r++) {
                float p = Ss[(warp * 8 + r) * 33 + kk];
                acc[r][0] += p * vv.x; acc[r][1] += p * vv.y;
                acc[r][2] += p * vv.z; acc[r][3] += p * vv.w;
            }
        }
    }
#pragma unroll
    for (int r = 0; r < 8; r++) {
        int R = q0 + warp * 8 + r;
        float inv = 1.0f / l_i[r];
        float4 o4 = make_float4(acc[r][0] * inv, acc[r][1] * inv,
                                acc[r][2] * inv, acc[r][3] * inv);
        *(float4*)(O + ((size_t)(b * SEQ + R)) * DIM + h * HD + lane * 4) = o4;
    }
}

// ---------------------------------------------------------------------------
extern "C" void kernel_launch(void* const* d_in, const int* in_sizes, int n_in,
                              void* d_out, int out_size)
{
    (void)in_sizes; (void)n_in; (void)out_size;
    const float* x     = (const float*)d_in[0];
    const float* ctx   = (const float*)d_in[1];
    const float* cosb  = (const float*)d_in[2];
    const float* sinb  = (const float*)d_in[3];
    const float* wq    = (const float*)d_in[4];
    const float* bq    = (const float*)d_in[5];
    const float* wk    = (const float*)d_in[6];
    const float* bk    = (const float*)d_in[7];
    const float* wv    = (const float*)d_in[8];
    const float* bv    = (const float*)d_in[9];
    const float* wqc   = (const float*)d_in[10];
    const float* bqc   = (const float*)d_in[11];
    const float* wkc   = (const float*)d_in[12];
    const float* bkc   = (const float*)d_in[13];
    const float* wvc   = (const float*)d_in[14];
    const float* bvc   = (const float*)d_in[15];
    const float* w_out = (const float*)d_in[16];
    const float* b_out = (const float*)d_in[17];
    const float* w_add = (const float*)d_in[18];
    const float* b_add = (const float*)d_in[19];
    const float* g_q   = (const float*)d_in[20];
    const float* g_k   = (const float*)d_in[21];
    const float* g_qc  = (const float*)d_in[22];
    const float* g_kc  = (const float*)d_in[23];
    float* out = (float*)d_out;

    float *QJ, *KJ, *VJ, *AO;
    cudaGetSymbolAddress((void**)&QJ, g_QJ);
    cudaGetSymbolAddress((void**)&KJ, g_KJ);
    cudaGetSymbolAddress((void**)&VJ, g_VJ);
    cudaGetSymbolAddress((void**)&AO, g_AO);

    cudaFuncSetAttribute(mma_gemm_kernel,
                         cudaFuncAttributeMaxDynamicSharedMemorySize, GEMM_SMEM_BYTES);
    cudaFuncSetAttribute(flash_kernel,
                         cudaFuncAttributeMaxDynamicSharedMemorySize, FLASH_SMEM_BYTES);

    dim3 gImg(DIM / 128, (BB * S_IMG) / 128);   // (24, 16)
    dim3 gTxt(DIM / 128, (BB * S_TXT) / 128);   // (24, 8)

    // QKV projections
    mma_gemm_kernel<<<gImg, 256, GEMM_SMEM_BYTES>>>(x,   S_IMG, 0, S_IMG, wq,  bq,  QJ, SEQ, S_TXT);
    mma_gemm_kernel<<<gTxt, 256, GEMM_SMEM_BYTES>>>(ctx, S_TXT, 0, S_TXT, wqc, bqc, QJ, SEQ, 0);
    mma_gemm_kernel<<<gImg, 256, GEMM_SMEM_BYTES>>>(x,   S_IMG, 0, S_IMG, wk,  bk,  KJ, SEQ, S_TXT);
    mma_gemm_kernel<<<gTxt, 256, GEMM_SMEM_BYTES>>>(ctx, S_TXT, 0, S_TXT, wkc, bkc, KJ, SEQ, 0);
    mma_gemm_kernel<<<gImg, 256, GEMM_SMEM_BYTES>>>(x,   S_IMG, 0, S_IMG, wv,  bv,  VJ, SEQ, S_TXT);
    mma_gemm_kernel<<<gTxt, 256, GEMM_SMEM_BYTES>>>(ctx, S_TXT, 0, S_TXT, wvc, bvc, VJ, SEQ, 0);

    rmsrope_kernel<<<BB * SEQ * HEADS, 128>>>(QJ, KJ, cosb, sinb, g_q, g_k, g_qc, g_kc);

    flash_kernel<<<dim3(SEQ / FBM, BB * HEADS), 256, FLASH_SMEM_BYTES>>>(QJ, KJ, VJ, AO);

    // Output projections: txt then img
    mma_gemm_kernel<<<gTxt, 256, GEMM_SMEM_BYTES>>>(AO, SEQ, 0,     S_TXT, w_add, b_add, out, S_TXT, 0);
    mma_gemm_kernel<<<gImg, 256, GEMM_SMEM_BYTES>>>(AO, SEQ, S_TXT, S_IMG, w_out, b_out,
                                                    out + (size_t)BB * S_TXT * DIM, S_IMG, 0);
}

// round 5
// speedup vs baseline: 1.8742x; 1.0918x over previous
#include <cuda_runtime.h>
#include <cuda_bf16.h>
#include <cstdint>
#include <math.h>

#define BB 2
#define S_IMG 1024
#define S_TXT 512
#define SEQ 1536
#define DIM 3072
#define HEADS 24
#define HD 128
#define EPSF 1e-6f
#define SCALEF 0.08838834764831845f

// Scratch (device globals -- no allocation allowed)
__device__ float g_QJ[BB * SEQ * DIM];
__device__ float g_KJ[BB * SEQ * DIM];
__device__ float g_VJ[BB * SEQ * DIM];
__device__ float g_AO[BB * SEQ * DIM];
// bf16 hi/lo split scratch
__device__ __nv_bfloat16 g_Whi[8 * DIM * DIM];
__device__ __nv_bfloat16 g_Wlo[8 * DIM * DIM];
__device__ __nv_bfloat16 g_Xhi[BB * SEQ * DIM];
__device__ __nv_bfloat16 g_Xlo[BB * SEQ * DIM];

// ===========================================================================
// helpers
// ===========================================================================
__device__ __forceinline__ uint32_t smem_u32(const void* p) {
    uint32_t a;
    asm("{ .reg .u64 t; cvta.to.shared.u64 t, %1; cvt.u32.u64 %0, t; }"
        : "=r"(a) : "l"(p));
    return a;
}
#define LDM4(r, a) \
    asm volatile("ldmatrix.sync.aligned.m8n8.x4.shared.b16 {%0,%1,%2,%3}, [%4];" \
        : "=r"((r)[0]), "=r"((r)[1]), "=r"((r)[2]), "=r"((r)[3]) : "r"(a))
#define LDM4T(r, a) \
    asm volatile("ldmatrix.sync.aligned.m8n8.x4.trans.shared.b16 {%0,%1,%2,%3}, [%4];" \
        : "=r"((r)[0]), "=r"((r)[1]), "=r"((r)[2]), "=r"((r)[3]) : "r"(a))
#define MMA_BF16(d, a, b0, b1) \
    asm volatile("mma.sync.aligned.m16n8k16.row.col.f32.bf16.bf16.f32 " \
        "{%0,%1,%2,%3}, {%4,%5,%6,%7}, {%8,%9}, {%0,%1,%2,%3};" \
        : "+f"((d)[0]), "+f"((d)[1]), "+f"((d)[2]), "+f"((d)[3]) \
        : "r"((a)[0]), "r"((a)[1]), "r"((a)[2]), "r"((a)[3]), "r"(b0), "r"(b1))
#define CPA16(dst, src) \
    asm volatile("cp.async.cg.shared.global [%0], [%1], 16;" :: "r"(dst), "l"(src))
#define CP_COMMIT() asm volatile("cp.async.commit_group;" ::: "memory")
#define CP_WAIT(n)  asm volatile("cp.async.wait_group %0;" :: "n"(n) : "memory")

__device__ __forceinline__ void split_bf16x4(float4 v, uint2& ph, uint2& pl) {
    __nv_bfloat16 h0 = __float2bfloat16(v.x);
    __nv_bfloat16 h1 = __float2bfloat16(v.y);
    __nv_bfloat16 h2 = __float2bfloat16(v.z);
    __nv_bfloat16 h3 = __float2bfloat16(v.w);
    __nv_bfloat16 l0 = __float2bfloat16(v.x - __bfloat162float(h0));
    __nv_bfloat16 l1 = __float2bfloat16(v.y - __bfloat162float(h1));
    __nv_bfloat16 l2 = __float2bfloat16(v.z - __bfloat162float(h2));
    __nv_bfloat16 l3 = __float2bfloat16(v.w - __bfloat162float(h3));
    ph.x = ((uint32_t)__bfloat16_as_ushort(h1) << 16) | __bfloat16_as_ushort(h0);
    ph.y = ((uint32_t)__bfloat16_as_ushort(h3) << 16) | __bfloat16_as_ushort(h2);
    pl.x = ((uint32_t)__bfloat16_as_ushort(l1) << 16) | __bfloat16_as_ushort(l0);
    pl.y = ((uint32_t)__bfloat16_as_ushort(l3) << 16) | __bfloat16_as_ushort(l2);
}

// ---------------------------------------------------------------------------
// fp32 -> bf16 hi/lo split conversion kernels
// ---------------------------------------------------------------------------
__global__ void __launch_bounds__(256) split_kernel(
    const float4* __restrict__ src, uint2* __restrict__ hi, uint2* __restrict__ lo, int n4)
{
    int i = blockIdx.x * 256 + threadIdx.x;
    if (i < n4) {
        uint2 ph, pl;
        split_bf16x4(src[i], ph, pl);
        hi[i] = ph; lo[i] = pl;
    }
}

// src [BB][rpb][DIM] -> dst joint rows (b*SEQ + dst_off + s)
__global__ void __launch_bounds__(256) split_act_kernel(
    const float4* __restrict__ src, uint2* __restrict__ hi, uint2* __restrict__ lo,
    int rpb, int dst_off)
{
    int i = blockIdx.x * 256 + threadIdx.x;
    int n4 = BB * rpb * (DIM / 4);
    if (i < n4) {
        int q = i % (DIM / 4);
        int row = i / (DIM / 4);
        int b = row / rpb, s = row % rpb;
        int dst = (b * SEQ + dst_off + s) * (DIM / 4) + q;
        uint2 ph, pl;
        split_bf16x4(src[i], ph, pl);
        hi[dst] = ph; lo[dst] = pl;
    }
}

// ===========================================================================
// bf16-split GEMM via mma.sync + cp.async 3-stage pipeline.
// C[128x128] tile; inputs preconverted bf16 hi/lo.
// 3 passes: Ahi*Bhi + Ahi*Blo + Alo*Bhi (fp32 accum). KC=32.
// A rows padded to 80B, B rows to 272B (conflict-free ldmatrix, R4-validated).
// ===========================================================================
#define KC 32
#define CHUNKS (DIM / KC)                  // 96
#define A_ST2 80
#define B_ST2 272
#define A_TILE_B (128 * A_ST2)             // 10240
#define B_TILE_B (32 * B_ST2)              // 8704
#define OFF_AHI 0
#define OFF_ALO A_TILE_B
#define OFF_BHI (2 * A_TILE_B)
#define OFF_BLO (2 * A_TILE_B + B_TILE_B)
#define STAGE_B (2 * A_TILE_B + 2 * B_TILE_B)   // 37888
#define NSTAGE 3
#define GEMM_SMEM_BYTES (NSTAGE * STAGE_B)      // 113664

__global__ void __launch_bounds__(256) mma_gemm_kernel(
    const __nv_bfloat16* __restrict__ Ahi_g, const __nv_bfloat16* __restrict__ Alo_g,
    int a_off, int rpb,
    const __nv_bfloat16* __restrict__ Whi, const __nv_bfloat16* __restrict__ Wlo,
    const float* __restrict__ bias,
    float* __restrict__ C_base, int c_seq, int c_off)
{
    extern __shared__ __align__(128) char smem[];
    const uint32_t sbase = smem_u32(smem);
    const int tid = threadIdx.x;
    const int wid = tid >> 5, lane = tid & 31;
    const int warp_m = wid & 3;
    const int warp_n = wid >> 2;

    const int row0 = blockIdx.y * 128;
    const int col0 = blockIdx.x * 128;
    const int b  = row0 / rpb;
    const int s0 = row0 % rpb;
    const __nv_bfloat16* Ahi = Ahi_g + (size_t)(b * SEQ + a_off + s0) * DIM;
    const __nv_bfloat16* Alo = Alo_g + (size_t)(b * SEQ + a_off + s0) * DIM;
    float* C = C_base + (size_t)(b * c_seq + c_off + s0) * DIM;

    // per-thread cp.async source/dest precompute
    const int fa = tid, fa2 = tid + 256;           // A chunk ids (row=f>>2, c16=f&3)
    const int fb = tid, fb2 = tid + 256;           // B chunk ids (krow=f>>4, c16=f&15)

#define ISSUE(c) do { \
    const int k0 = (c) * KC; \
    const uint32_t stb = sbase + ((c) % NSTAGE) * STAGE_B; \
    { int f = fa;  uint32_t d = stb + OFF_AHI + (uint32_t)(f >> 2) * A_ST2 + (f & 3) * 16; \
      size_t so = (size_t)(f >> 2) * DIM + k0 + ((f & 3) << 3); \
      CPA16(d, (const void*)(Ahi + so)); \
      CPA16(d + A_TILE_B, (const void*)(Alo + so)); } \
    { int f = fa2; uint32_t d = stb + OFF_AHI + (uint32_t)(f >> 2) * A_ST2 + (f & 3) * 16; \
      size_t so = (size_t)(f >> 2) * DIM + k0 + ((f & 3) << 3); \
      CPA16(d, (const void*)(Ahi + so)); \
      CPA16(d + A_TILE_B, (const void*)(Alo + so)); } \
    { int f = fb;  uint32_t d = stb + OFF_BHI + (uint32_t)(f >> 4) * B_ST2 + (f & 15) * 16; \
      size_t so = (size_t)(k0 + (f >> 4)) * DIM + col0 + ((f & 15) << 3); \
      CPA16(d, (const void*)(Whi + so)); \
      CPA16(d + B_TILE_B, (const void*)(Wlo + so)); } \
    { int f = fb2; uint32_t d = stb + OFF_BHI + (uint32_t)(f >> 4) * B_ST2 + (f & 15) * 16; \
      size_t so = (size_t)(k0 + (f >> 4)) * DIM + col0 + ((f & 15) << 3); \
      CPA16(d, (const void*)(Whi + so)); \
      CPA16(d + B_TILE_B, (const void*)(Wlo + so)); } \
    CP_COMMIT(); \
} while (0)

    float acc[2][8][4];
#pragma unroll
    for (int i = 0; i < 2; i++)
#pragma unroll
        for (int j = 0; j < 8; j++)
#pragma unroll
            for (int k = 0; k < 4; k++) acc[i][j][k] = 0.f;

    const uint32_t a_row  = (uint32_t)(warp_m * 32 + (lane & 15));
    const uint32_t a_col8 = (uint32_t)((lane >> 4) * 16);
    const uint32_t b_row  = (uint32_t)(lane & 15);
    const uint32_t b_col8 = (uint32_t)((warp_n * 64 + ((lane >> 4) << 3)) * 2);

#define COMPUTE(sidx) do { \
    const uint32_t sb = sbase + (sidx) * STAGE_B; \
    _Pragma("unroll") \
    for (int ks = 0; ks < 2; ks++) { \
        uint32_t ah[2][4], al[2][4]; \
        _Pragma("unroll") \
        for (int mt = 0; mt < 2; mt++) { \
            uint32_t ad = sb + OFF_AHI + (a_row + mt * 16) * A_ST2 + ks * 32 + a_col8; \
            LDM4(ah[mt], ad); \
            LDM4(al[mt], ad + A_TILE_B); \
        } \
        _Pragma("unroll") \
        for (int ng = 0; ng < 4; ng++) { \
            uint32_t bh[4], bl[4]; \
            uint32_t bd = sb + OFF_BHI + (ks * 16 + b_row) * B_ST2 + b_col8 + ng * 32; \
            LDM4T(bh, bd); \
            LDM4T(bl, bd + B_TILE_B); \
            _Pragma("unroll") \
            for (int mt = 0; mt < 2; mt++) { \
                MMA_BF16(acc[mt][ng * 2 + 0], ah[mt], bh[0], bh[1]); \
                MMA_BF16(acc[mt][ng * 2 + 0], ah[mt], bl[0], bl[1]); \
                MMA_BF16(acc[mt][ng * 2 + 0], al[mt], bh[0], bh[1]); \
                MMA_BF16(acc[mt][ng * 2 + 1], ah[mt], bh[2], bh[3]); \
                MMA_BF16(acc[mt][ng * 2 + 1], ah[mt], bl[2], bl[3]); \
                MMA_BF16(acc[mt][ng * 2 + 1], al[mt], bh[2], bh[3]); \
            } \
        } \
    } \
} while (0)

    // prologue: fill 2 stages
    ISSUE(0);
    ISSUE(1);
    for (int c = 0; c < CHUNKS; c++) {
        if (c == CHUNKS - 1) CP_WAIT(0); else CP_WAIT(1);
        __syncthreads();
        if (c + 2 < CHUNKS) ISSUE(c + 2);
        COMPUTE(c % NSTAGE);
        // next iteration's ISSUE targets buffer (c+3)%3 == c%3; the wait+sync at
        // the top of iteration c+1 guarantees every thread finished COMPUTE(c).
    }

    const int m_base = warp_m * 32;
    const int n_base = col0 + warp_n * 64;
#pragma unroll
    for (int mt = 0; mt < 2; mt++) {
#pragma unroll
        for (int nt = 0; nt < 8; nt++) {
            int r  = m_base + mt * 16 + (lane >> 2);
            int cc = n_base + nt * 8 + ((lane & 3) << 1);
            float b0 = bias[cc], b1 = bias[cc + 1];
            float2 v0 = make_float2(acc[mt][nt][0] + b0, acc[mt][nt][1] + b1);
            float2 v1 = make_float2(acc[mt][nt][2] + b0, acc[mt][nt][3] + b1);
            *(float2*)(C + (size_t)r * DIM + cc) = v0;
            *(float2*)(C + (size_t)(r + 8) * DIM + cc) = v1;
        }
    }
#undef ISSUE
#undef COMPUTE
}

// ---------------------------------------------------------------------------
// Fused RMS-norm + RoPE (unchanged)
// ---------------------------------------------------------------------------
__global__ void __launch_bounds__(128) rmsrope_kernel(
    float* __restrict__ Q, float* __restrict__ K,
    const float* __restrict__ cosb, const float* __restrict__ sinb,
    const float* __restrict__ gq, const float* __restrict__ gk,
    const float* __restrict__ gqc, const float* __restrict__ gkc)
{
    const int idx = blockIdx.x;
    const int h = idx % HEADS;
    const int s = (idx / HEADS) % SEQ;
    const int b = idx / (HEADS * SEQ);
    const int d = threadIdx.x;
    const size_t off = ((size_t)(b * SEQ + s)) * DIM + h * HD + d;
    __shared__ float sh[HD];
    __shared__ float red[4];
    const float c  = cosb[s * (HD / 2) + (d >> 1)];
    const float sn = sinb[s * (HD / 2) + (d >> 1)];
    const bool txt = (s < S_TXT);

    {
        float v = Q[off];
        float sq = v * v;
#pragma unroll
        for (int o = 16; o > 0; o >>= 1) sq += __shfl_xor_sync(0xffffffffu, sq, o);
        if ((d & 31) == 0) red[d >> 5] = sq;
        __syncthreads();
        float mean = (red[0] + red[1] + red[2] + red[3]) * (1.0f / HD);
        float scl = rsqrtf(mean + EPSF) * (txt ? gqc[d] : gq[d]);
        sh[d] = v * scl;
        __syncthreads();
        float out = ((d & 1) == 0) ? (sh[d] * c - sh[d + 1] * sn)
                                   : (sh[d - 1] * sn + sh[d] * c);
        Q[off] = out;
    }
    __syncthreads();
    {
        float v = K[off];
        float sq = v * v;
#pragma unroll
        for (int o = 16; o > 0; o >>= 1) sq += __shfl_xor_sync(0xffffffffu, sq, o);
        if ((d & 31) == 0) red[d >> 5] = sq;
        __syncthreads();
        float mean = (red[0] + red[1] + red[2] + red[3]) * (1.0f / HD);
        float scl = rsqrtf(mean + EPSF) * (txt ? gkc[d] : gk[d]);
        sh[d] = v * scl;
        __syncthreads();
        float out = ((d & 1) == 0) ? (sh[d] * c - sh[d + 1] * sn)
                                   : (sh[d - 1] * sn + sh[d] * c);
        K[off] = out;
    }
}

// ---------------------------------------------------------------------------
// Flash attention fp32 (unchanged from R2/R4 pass)
// ---------------------------------------------------------------------------
#define FBM 64
#define FBN 32
#define QS_ST 129
#define KS_ST 129
#define QS_ELEMS (FBM * QS_ST)
#define KV_ELEMS (FBN * KS_ST)
#define SS_ELEMS (FBM * 33)
#define FLASH_SMEM_BYTES ((QS_ELEMS + KV_ELEMS + SS_ELEMS) * 4)

__global__ void __launch_bounds__(256) flash_kernel(
    const float* __restrict__ Q, const float* __restrict__ K,
    const float* __restrict__ V, float* __restrict__ O)
{
    extern __shared__ __align__(16) float fsm[];
    float* Qs = fsm;
    float* KV = fsm + QS_ELEMS;
    float* Ss = fsm + QS_ELEMS + KV_ELEMS;

    const int tid = threadIdx.x;
    const int warp = tid >> 5, lane = tid & 31;
    const int qt = blockIdx.x;
    const int bh = blockIdx.y;
    const int b = bh / HEADS, h = bh % HEADS;
    const int q0 = qt * FBM;
    const float* Qg = Q + ((size_t)b * SEQ) * DIM + h * HD;
    const float* Kg = K + ((size_t)b * SEQ) * DIM + h * HD;
    const float* Vg = V + ((size_t)b * SEQ) * DIM + h * HD;

    for (int i = tid; i < FBM * 32; i += 256) {
        int r = i >> 5, d4 = (i & 31) << 2;
        float4 v = *(const float4*)(Qg + (size_t)(q0 + r) * DIM + d4);
        Qs[r * QS_ST + d4 + 0] = v.x; Qs[r * QS_ST + d4 + 1] = v.y;
        Qs[r * QS_ST + d4 + 2] = v.z; Qs[r * QS_ST + d4 + 3] = v.w;
    }

    const int sr = (tid >> 4) << 2;
    const int sc = (tid & 15) << 1;

    float acc[8][4];
#pragma unroll
    for (int r = 0; r < 8; r++) { acc[r][0] = acc[r][1] = acc[r][2] = acc[r][3] = 0.f; }
    float m_i[8], l_i[8];
#pragma unroll
    for (int r = 0; r < 8; r++) { m_i[r] = -1e30f; l_i[r] = 0.f; }

    for (int kt = 0; kt < SEQ / FBN; kt++) {
        const int k0 = kt * FBN;
        __syncthreads();
        for (int i = tid; i < FBN * 32; i += 256) {
            int r = i >> 5, d4 = (i & 31) << 2;
            float4 v = *(const float4*)(Kg + (size_t)(k0 + r) * DIM + d4);
            KV[r * KS_ST + d4 + 0] = v.x; KV[r * KS_ST + d4 + 1] = v.y;
            KV[r * KS_ST + d4 + 2] = v.z; KV[r * KS_ST + d4 + 3] = v.w;
        }
        __syncthreads();
        float sacc[4][2];
#pragma unroll
        for (int i = 0; i < 4; i++) { sacc[i][0] = 0.f; sacc[i][1] = 0.f; }
#pragma unroll 4
        for (int d = 0; d < HD; d++) {
            float a0 = Qs[(sr + 0) * QS_ST + d];
            float a1 = Qs[(sr + 1) * QS_ST + d];
            float a2 = Qs[(sr + 2) * QS_ST + d];
            float a3 = Qs[(sr + 3) * QS_ST + d];
            float b0 = KV[(sc + 0) * KS_ST + d];
            float b1 = KV[(sc + 1) * KS_ST + d];
            sacc[0][0] += a0 * b0; sacc[0][1] += a0 * b1;
            sacc[1][0] += a1 * b0; sacc[1][1] += a1 * b1;
            sacc[2][0] += a2 * b0; sacc[2][1] += a2 * b1;
            sacc[3][0] += a3 * b0; sacc[3][1] += a3 * b1;
        }
#pragma unroll
        for (int i = 0; i < 4; i++) {
            Ss[(sr + i) * 33 + sc + 0] = sacc[i][0] * SCALEF;
            Ss[(sr + i) * 33 + sc + 1] = sacc[i][1] * SCALEF;
        }
        __syncthreads();
#pragma unroll
        for (int r = 0; r < 8; r++) {
            int R = warp * 8 + r;
            float s1 = Ss[R * 33 + lane];
            float mx = s1;
#pragma unroll
            for (int o = 16; o > 0; o >>= 1) mx = fmaxf(mx, __shfl_xor_sync(0xffffffffu, mx, o));
            float mn = fmaxf(m_i[r], mx);
            float f  = __expf(m_i[r] - mn);
            float p1 = __expf(s1 - mn);
            Ss[R * 33 + lane] = p1;
            float rs = p1;
#pragma unroll
            for (int o = 16; o > 0; o >>= 1) rs += __shfl_xor_sync(0xffffffffu, rs, o);
            l_i[r] = l_i[r] * f + rs;
            m_i[r] = mn;
            acc[r][0] *= f; acc[r][1] *= f; acc[r][2] *= f; acc[r][3] *= f;
        }
        __syncthreads();
        for (int i = tid; i < FBN * 32; i += 256) {
            int r = i >> 5, d4 = (i & 31) << 2;
            float4 v = *(const float4*)(Vg + (size_t)(k0 + r) * DIM + d4);
            *(float4*)&KV[r * 128 + d4] = v;
        }
        __syncthreads();
#pragma unroll 2
        for (int kk = 0; kk < FBN; kk++) {
            float4 vv = *(const float4*)&KV[kk * 128 + lane * 4];
#pragma unroll
            for (int r = 0; r < 8; r++) {
                float p = Ss[(warp * 8 + r) * 33 + kk];
                acc[r][0] += p * vv.x; acc[r][1] += p * vv.y;
                acc[r][2] += p * vv.z; acc[r][3] += p * vv.w;
            }
        }
    }
#pragma unroll
    for (int r = 0; r < 8; r++) {
        int R = q0 + warp * 8 + r;
        float inv = 1.0f / l_i[r];
        float4 o4 = make_float4(acc[r][0] * inv, acc[r][1] * inv,
                                acc[r][2] * inv, acc[r][3] * inv);
        *(float4*)(O + ((size_t)(b * SEQ + R)) * DIM + h * HD + lane * 4) = o4;
    }
}

// ---------------------------------------------------------------------------
extern "C" void kernel_launch(void* const* d_in, const int* in_sizes, int n_in,
                              void* d_out, int out_size)
{
    (void)in_sizes; (void)n_in; (void)out_size;
    const float* x     = (const float*)d_in[0];
    const float* ctx   = (const float*)d_in[1];
    const float* cosb  = (const float*)d_in[2];
    const float* sinb  = (const float*)d_in[3];
    const float* wptr[8] = {
        (const float*)d_in[4],   // wq
        (const float*)d_in[6],   // wk
        (const float*)d_in[8],   // wv
        (const float*)d_in[10],  // wqc
        (const float*)d_in[12],  // wkc
        (const float*)d_in[14],  // wvc
        (const float*)d_in[16],  // w_out
        (const float*)d_in[18],  // w_add_out
    };
    const float* bq    = (const float*)d_in[5];
    const float* bk    = (const float*)d_in[7];
    const float* bv    = (const float*)d_in[9];
    const float* bqc   = (const float*)d_in[11];
    const float* bkc   = (const float*)d_in[13];
    const float* bvc   = (const float*)d_in[15];
    const float* b_out = (const float*)d_in[17];
    const float* b_add = (const float*)d_in[19];
    const float* g_q   = (const float*)d_in[20];
    const float* g_k   = (const float*)d_in[21];
    const float* g_qc  = (const float*)d_in[22];
    const float* g_kc  = (const float*)d_in[23];
    float* out = (float*)d_out;

    float *QJ, *KJ, *VJ, *AO;
    __nv_bfloat16 *Whi, *Wlo, *Xhi, *Xlo;
    cudaGetSymbolAddress((void**)&QJ, g_QJ);
    cudaGetSymbolAddress((void**)&KJ, g_KJ);
    cudaGetSymbolAddress((void**)&VJ, g_VJ);
    cudaGetSymbolAddress((void**)&AO, g_AO);
    cudaGetSymbolAddress((void**)&Whi, g_Whi);
    cudaGetSymbolAddress((void**)&Wlo, g_Wlo);
    cudaGetSymbolAddress((void**)&Xhi, g_Xhi);
    cudaGetSymbolAddress((void**)&Xlo, g_Xlo);

    cudaFuncSetAttribute(mma_gemm_kernel,
                         cudaFuncAttributeMaxDynamicSharedMemorySize, GEMM_SMEM_BYTES);
    cudaFuncSetAttribute(flash_kernel,
                         cudaFuncAttributeMaxDynamicSharedMemorySize, FLASH_SMEM_BYTES);

    const size_t WSZ = (size_t)DIM * DIM;
    const int WN4 = DIM * DIM / 4;

    // ---- preconvert weights to bf16 hi/lo ----
    for (int w = 0; w < 8; w++)
        split_kernel<<<(WN4 + 255) / 256, 256>>>(
            (const float4*)wptr[w], (uint2*)(Whi + w * WSZ), (uint2*)(Wlo + w * WSZ), WN4);

    // ---- preconvert activations into joint layout (ctx rows 0..511, x rows 512..1535) ----
    split_act_kernel<<<(BB * S_TXT * (DIM / 4) + 255) / 256, 256>>>(
        (const float4*)ctx, (uint2*)Xhi, (uint2*)Xlo, S_TXT, 0);
    split_act_kernel<<<(BB * S_IMG * (DIM / 4) + 255) / 256, 256>>>(
        (const float4*)x, (uint2*)Xhi, (uint2*)Xlo, S_IMG, S_TXT);

    dim3 gImg(DIM / 128, (BB * S_IMG) / 128);   // (24, 16)
    dim3 gTxt(DIM / 128, (BB * S_TXT) / 128);   // (24, 8)

    // QKV projections
    mma_gemm_kernel<<<gImg, 256, GEMM_SMEM_BYTES>>>(Xhi, Xlo, S_TXT, S_IMG,
        Whi + 0 * WSZ, Wlo + 0 * WSZ, bq,  QJ, SEQ, S_TXT);
    mma_gemm_kernel<<<gTxt, 256, GEMM_SMEM_BYTES>>>(Xhi, Xlo, 0, S_TXT,
        Whi + 3 * WSZ, Wlo + 3 * WSZ, bqc, QJ, SEQ, 0);
    mma_gemm_kernel<<<gImg, 256, GEMM_SMEM_BYTES>>>(Xhi, Xlo, S_TXT, S_IMG,
        Whi + 1 * WSZ, Wlo + 1 * WSZ, bk,  KJ, SEQ, S_TXT);
    mma_gemm_kernel<<<gTxt, 256, GEMM_SMEM_BYTES>>>(Xhi, Xlo, 0, S_TXT,
        Whi + 4 * WSZ, Wlo + 4 * WSZ, bkc, KJ, SEQ, 0);
    mma_gemm_kernel<<<gImg, 256, GEMM_SMEM_BYTES>>>(Xhi, Xlo, S_TXT, S_IMG,
        Whi + 2 * WSZ, Wlo + 2 * WSZ, bv,  VJ, SEQ, S_TXT);
    mma_gemm_kernel<<<gTxt, 256, GEMM_SMEM_BYTES>>>(Xhi, Xlo, 0, S_TXT,
        Whi + 5 * WSZ, Wlo + 5 * WSZ, bvc, VJ, SEQ, 0);

    rmsrope_kernel<<<BB * SEQ * HEADS, 128>>>(QJ, KJ, cosb, sinb, g_q, g_k, g_qc, g_kc);

    flash_kernel<<<dim3(SEQ / FBM, BB * HEADS), 256, FLASH_SMEM_BYTES>>>(QJ, KJ, VJ, AO);

    // reconvert attention output (joint layout, txt rows first)
    split_act_kernel<<<(BB * SEQ * (DIM / 4) + 255) / 256, 256>>>(
        (const float4*)AO, (uint2*)Xhi, (uint2*)Xlo, SEQ, 0);

    // output projections: txt (joint rows 0..511) then img (joint rows 512..1535)
    mma_gemm_kernel<<<gTxt, 256, GEMM_SMEM_BYTES>>>(Xhi, Xlo, 0, S_TXT,
        Whi + 7 * WSZ, Wlo + 7 * WSZ, b_add, out, S_TXT, 0);
    mma_gemm_kernel<<<gImg, 256, GEMM_SMEM_BYTES>>>(Xhi, Xlo, S_TXT, S_IMG,
        Whi + 6 * WSZ, Wlo + 6 * WSZ, b_out,
        out + (size_t)BB * S_TXT * DIM, S_IMG, 0);
}

// round 6
// speedup vs baseline: 3.1895x; 1.7018x over previous
#include <cuda_runtime.h>
#include <cuda_bf16.h>
#include <cstdint>
#include <math.h>

#define BB 2
#define S_IMG 1024
#define S_TXT 512
#define SEQ 1536
#define DIM 3072
#define HEADS 24
#define HD 128
#define EPSF 1e-6f
#define SCALEF 0.08838834764831845f

// Scratch (device globals -- no allocation allowed)
__device__ float g_QJ[BB * SEQ * DIM];
__device__ float g_KJ[BB * SEQ * DIM];
__device__ float g_VJ[BB * SEQ * DIM];
__device__ __nv_bfloat16 g_Whi[8 * DIM * DIM];
__device__ __nv_bfloat16 g_Wlo[8 * DIM * DIM];
__device__ __nv_bfloat16 g_Xhi[BB * SEQ * DIM];
__device__ __nv_bfloat16 g_Xlo[BB * SEQ * DIM];
__device__ __nv_bfloat16 g_Qhi[BB * SEQ * DIM];
__device__ __nv_bfloat16 g_Qlo[BB * SEQ * DIM];
__device__ __nv_bfloat16 g_Khi[BB * SEQ * DIM];
__device__ __nv_bfloat16 g_Klo[BB * SEQ * DIM];
__device__ __nv_bfloat16 g_Vhi[BB * SEQ * DIM];
__device__ __nv_bfloat16 g_Vlo[BB * SEQ * DIM];

// ===========================================================================
// helpers
// ===========================================================================
__device__ __forceinline__ uint32_t smem_u32(const void* p) {
    uint32_t a;
    asm("{ .reg .u64 t; cvta.to.shared.u64 t, %1; cvt.u32.u64 %0, t; }"
        : "=r"(a) : "l"(p));
    return a;
}
#define LDM4(r, a) \
    asm volatile("ldmatrix.sync.aligned.m8n8.x4.shared.b16 {%0,%1,%2,%3}, [%4];" \
        : "=r"((r)[0]), "=r"((r)[1]), "=r"((r)[2]), "=r"((r)[3]) : "r"(a))
#define LDM4T(r, a) \
    asm volatile("ldmatrix.sync.aligned.m8n8.x4.trans.shared.b16 {%0,%1,%2,%3}, [%4];" \
        : "=r"((r)[0]), "=r"((r)[1]), "=r"((r)[2]), "=r"((r)[3]) : "r"(a))
#define MMA_BF16(d, a, b0, b1) \
    asm volatile("mma.sync.aligned.m16n8k16.row.col.f32.bf16.bf16.f32 " \
        "{%0,%1,%2,%3}, {%4,%5,%6,%7}, {%8,%9}, {%0,%1,%2,%3};" \
        : "+f"((d)[0]), "+f"((d)[1]), "+f"((d)[2]), "+f"((d)[3]) \
        : "r"((a)[0]), "r"((a)[1]), "r"((a)[2]), "r"((a)[3]), "r"(b0), "r"(b1))
#define MMA_BF16_2(d, a0r, a1r, a2r, a3r, b0, b1) \
    asm volatile("mma.sync.aligned.m16n8k16.row.col.f32.bf16.bf16.f32 " \
        "{%0,%1,%2,%3}, {%4,%5,%6,%7}, {%8,%9}, {%0,%1,%2,%3};" \
        : "+f"((d)[0]), "+f"((d)[1]), "+f"((d)[2]), "+f"((d)[3]) \
        : "r"(a0r), "r"(a1r), "r"(a2r), "r"(a3r), "r"(b0), "r"(b1))
#define CPA16(dst, src) \
    asm volatile("cp.async.cg.shared.global [%0], [%1], 16;" :: "r"(dst), "l"(src))
#define CP_COMMIT() asm volatile("cp.async.commit_group;" ::: "memory")
#define CP_WAIT(n)  asm volatile("cp.async.wait_group %0;" :: "n"(n) : "memory")

__device__ __forceinline__ void split_bf16x4(float4 v, uint2& ph, uint2& pl) {
    __nv_bfloat16 h0 = __float2bfloat16(v.x);
    __nv_bfloat16 h1 = __float2bfloat16(v.y);
    __nv_bfloat16 h2 = __float2bfloat16(v.z);
    __nv_bfloat16 h3 = __float2bfloat16(v.w);
    __nv_bfloat16 l0 = __float2bfloat16(v.x - __bfloat162float(h0));
    __nv_bfloat16 l1 = __float2bfloat16(v.y - __bfloat162float(h1));
    __nv_bfloat16 l2 = __float2bfloat16(v.z - __bfloat162float(h2));
    __nv_bfloat16 l3 = __float2bfloat16(v.w - __bfloat162float(h3));
    ph.x = ((uint32_t)__bfloat16_as_ushort(h1) << 16) | __bfloat16_as_ushort(h0);
    ph.y = ((uint32_t)__bfloat16_as_ushort(h3) << 16) | __bfloat16_as_ushort(h2);
    pl.x = ((uint32_t)__bfloat16_as_ushort(l1) << 16) | __bfloat16_as_ushort(l0);
    pl.y = ((uint32_t)__bfloat16_as_ushort(l3) << 16) | __bfloat16_as_ushort(l2);
}
__device__ __forceinline__ uint32_t pack_split2(float a, float b, uint32_t& lo_out) {
    __nv_bfloat16 ha = __float2bfloat16(a);
    __nv_bfloat16 hb = __float2bfloat16(b);
    __nv_bfloat16 la = __float2bfloat16(a - __bfloat162float(ha));
    __nv_bfloat16 lb = __float2bfloat16(b - __bfloat162float(hb));
    lo_out = ((uint32_t)__bfloat16_as_ushort(lb) << 16) | __bfloat16_as_ushort(la);
    return ((uint32_t)__bfloat16_as_ushort(hb) << 16) | __bfloat16_as_ushort(ha);
}

// ---------------------------------------------------------------------------
// fp32 -> bf16 hi/lo split conversion kernels
// ---------------------------------------------------------------------------
__global__ void __launch_bounds__(256) split_kernel(
    const float4* __restrict__ src, uint2* __restrict__ hi, uint2* __restrict__ lo, int n4)
{
    int i = blockIdx.x * 256 + threadIdx.x;
    if (i < n4) {
        uint2 ph, pl;
        split_bf16x4(src[i], ph, pl);
        hi[i] = ph; lo[i] = pl;
    }
}

// src [BB][rpb][DIM] -> dst joint rows (b*SEQ + dst_off + s)
__global__ void __launch_bounds__(256) split_act_kernel(
    const float4* __restrict__ src, uint2* __restrict__ hi, uint2* __restrict__ lo,
    int rpb, int dst_off)
{
    int i = blockIdx.x * 256 + threadIdx.x;
    int n4 = BB * rpb * (DIM / 4);
    if (i < n4) {
        int q = i % (DIM / 4);
        int row = i / (DIM / 4);
        int b = row / rpb, s = row % rpb;
        int dst = (b * SEQ + dst_off + s) * (DIM / 4) + q;
        uint2 ph, pl;
        split_bf16x4(src[i], ph, pl);
        hi[dst] = ph; lo[dst] = pl;
    }
}

// ===========================================================================
// bf16-split GEMM via mma.sync + cp.async 4-stage pipeline. z selects weight.
// ===========================================================================
#define KC 32
#define CHUNKS (DIM / KC)                  // 96
#define A_ST2 80
#define B_ST2 272
#define A_TILE_B (128 * A_ST2)
#define B_TILE_B (32 * B_ST2)
#define OFF_AHI 0
#define OFF_ALO A_TILE_B
#define OFF_BHI (2 * A_TILE_B)
#define OFF_BLO (2 * A_TILE_B + B_TILE_B)
#define STAGE_B (2 * A_TILE_B + 2 * B_TILE_B)   // 37888
#define NSTAGE 4
#define GEMM_SMEM_BYTES (NSTAGE * STAGE_B)      // 151552

__global__ void __launch_bounds__(256) mma_gemm_kernel(
    const __nv_bfloat16* __restrict__ Ahi_g, const __nv_bfloat16* __restrict__ Alo_g,
    int a_off, int rpb,
    const __nv_bfloat16* __restrict__ Whi_base, const __nv_bfloat16* __restrict__ Wlo_base,
    int w0, int w1, int w2,
    const float* bias0, const float* bias1, const float* bias2,
    float* C0, float* C1, float* C2,
    int c_seq, int c_off)
{
    extern __shared__ __align__(128) char smem[];
    const uint32_t sbase = smem_u32(smem);
    const int tid = threadIdx.x;
    const int wid = tid >> 5, lane = tid & 31;
    const int warp_m = wid & 3;
    const int warp_n = wid >> 2;
    const int z = blockIdx.z;

    const int widx = (z == 0) ? w0 : ((z == 1) ? w1 : w2);
    const float* bias = (z == 0) ? bias0 : ((z == 1) ? bias1 : bias2);
    float* C_base = (z == 0) ? C0 : ((z == 1) ? C1 : C2);
    const __nv_bfloat16* Whi = Whi_base + (size_t)widx * DIM * DIM;
    const __nv_bfloat16* Wlo = Wlo_base + (size_t)widx * DIM * DIM;

    const int row0 = blockIdx.y * 128;
    const int col0 = blockIdx.x * 128;
    const int b  = row0 / rpb;
    const int s0 = row0 % rpb;
    const __nv_bfloat16* Ahi = Ahi_g + (size_t)(b * SEQ + a_off + s0) * DIM;
    const __nv_bfloat16* Alo = Alo_g + (size_t)(b * SEQ + a_off + s0) * DIM;
    float* C = C_base + (size_t)(b * c_seq + c_off + s0) * DIM;

#define ISSUE(c) do { \
    const int k0 = (c) * KC; \
    const uint32_t stb = sbase + ((c) % NSTAGE) * STAGE_B; \
    _Pragma("unroll") \
    for (int i = 0; i < 2; i++) { \
        int f = tid + i * 256; \
        uint32_t d = stb + OFF_AHI + (uint32_t)(f >> 2) * A_ST2 + (f & 3) * 16; \
        size_t so = (size_t)(f >> 2) * DIM + k0 + ((f & 3) << 3); \
        CPA16(d, (const void*)(Ahi + so)); \
        CPA16(d + A_TILE_B, (const void*)(Alo + so)); \
        uint32_t db = stb + OFF_BHI + (uint32_t)(f >> 4) * B_ST2 + (f & 15) * 16; \
        size_t sb2 = (size_t)(k0 + (f >> 4)) * DIM + col0 + ((f & 15) << 3); \
        CPA16(db, (const void*)(Whi + sb2)); \
        CPA16(db + B_TILE_B, (const void*)(Wlo + sb2)); \
    } \
    CP_COMMIT(); \
} while (0)

    float acc[2][8][4];
#pragma unroll
    for (int i = 0; i < 2; i++)
#pragma unroll
        for (int j = 0; j < 8; j++)
#pragma unroll
            for (int k = 0; k < 4; k++) acc[i][j][k] = 0.f;

    const uint32_t a_row  = (uint32_t)(warp_m * 32 + (lane & 15));
    const uint32_t a_col8 = (uint32_t)((lane >> 4) * 16);
    const uint32_t b_row  = (uint32_t)(lane & 15);
    const uint32_t b_col8 = (uint32_t)((warp_n * 64 + ((lane >> 4) << 3)) * 2);

#define COMPUTE(sidx) do { \
    const uint32_t sb = sbase + (sidx) * STAGE_B; \
    _Pragma("unroll") \
    for (int ks = 0; ks < 2; ks++) { \
        uint32_t ah[2][4], al[2][4]; \
        _Pragma("unroll") \
        for (int mt = 0; mt < 2; mt++) { \
            uint32_t ad = sb + OFF_AHI + (a_row + mt * 16) * A_ST2 + ks * 32 + a_col8; \
            LDM4(ah[mt], ad); \
            LDM4(al[mt], ad + A_TILE_B); \
        } \
        _Pragma("unroll") \
        for (int ng = 0; ng < 4; ng++) { \
            uint32_t bh[4], bl[4]; \
            uint32_t bd = sb + OFF_BHI + (ks * 16 + b_row) * B_ST2 + b_col8 + ng * 32; \
            LDM4T(bh, bd); \
            LDM4T(bl, bd + B_TILE_B); \
            _Pragma("unroll") \
            for (int mt = 0; mt < 2; mt++) { \
                MMA_BF16(acc[mt][ng * 2 + 0], ah[mt], bh[0], bh[1]); \
                MMA_BF16(acc[mt][ng * 2 + 0], ah[mt], bl[0], bl[1]); \
                MMA_BF16(acc[mt][ng * 2 + 0], al[mt], bh[0], bh[1]); \
                MMA_BF16(acc[mt][ng * 2 + 1], ah[mt], bh[2], bh[3]); \
                MMA_BF16(acc[mt][ng * 2 + 1], ah[mt], bl[2], bl[3]); \
                MMA_BF16(acc[mt][ng * 2 + 1], al[mt], bh[2], bh[3]); \
            } \
        } \
    } \
} while (0)

    ISSUE(0); ISSUE(1); ISSUE(2);
    for (int c = 0; c < CHUNKS; c++) {
        if (c < CHUNKS - 2) { CP_WAIT(2); }
        else if (c == CHUNKS - 2) { CP_WAIT(1); }
        else { CP_WAIT(0); }
        __syncthreads();
        if (c + 3 < CHUNKS) ISSUE(c + 3);
        COMPUTE(c % NSTAGE);
    }

    const int m_base = warp_m * 32;
    const int n_base = col0 + warp_n * 64;
#pragma unroll
    for (int mt = 0; mt < 2; mt++) {
#pragma unroll
        for (int nt = 0; nt < 8; nt++) {
            int r  = m_base + mt * 16 + (lane >> 2);
            int cc = n_base + nt * 8 + ((lane & 3) << 1);
            float b0 = bias[cc], b1 = bias[cc + 1];
            float2 v0 = make_float2(acc[mt][nt][0] + b0, acc[mt][nt][1] + b1);
            float2 v1 = make_float2(acc[mt][nt][2] + b0, acc[mt][nt][3] + b1);
            *(float2*)(C + (size_t)r * DIM + cc) = v0;
            *(float2*)(C + (size_t)(r + 8) * DIM + cc) = v1;
        }
    }
#undef ISSUE
#undef COMPUTE
}

// ---------------------------------------------------------------------------
// Fused RMS-norm + RoPE; reads fp32 Q/K, writes bf16 hi/lo splits.
// ---------------------------------------------------------------------------
__global__ void __launch_bounds__(128) rmsrope_kernel(
    const float* __restrict__ Q, const float* __restrict__ K,
    __nv_bfloat16* __restrict__ Qhi, __nv_bfloat16* __restrict__ Qlo,
    __nv_bfloat16* __restrict__ Khi, __nv_bfloat16* __restrict__ Klo,
    const float* __restrict__ cosb, const float* __restrict__ sinb,
    const float* __restrict__ gq, const float* __restrict__ gk,
    const float* __restrict__ gqc, const float* __restrict__ gkc)
{
    const int idx = blockIdx.x;
    const int h = idx % HEADS;
    const int s = (idx / HEADS) % SEQ;
    const int b = idx / (HEADS * SEQ);
    const int d = threadIdx.x;
    const size_t off = ((size_t)(b * SEQ + s)) * DIM + h * HD + d;
    __shared__ float sh[HD];
    __shared__ float red[4];
    const float c  = cosb[s * (HD / 2) + (d >> 1)];
    const float sn = sinb[s * (HD / 2) + (d >> 1)];
    const bool txt = (s < S_TXT);

    {
        float v = Q[off];
        float sq = v * v;
#pragma unroll
        for (int o = 16; o > 0; o >>= 1) sq += __shfl_xor_sync(0xffffffffu, sq, o);
        if ((d & 31) == 0) red[d >> 5] = sq;
        __syncthreads();
        float mean = (red[0] + red[1] + red[2] + red[3]) * (1.0f / HD);
        float scl = rsqrtf(mean + EPSF) * (txt ? gqc[d] : gq[d]);
        sh[d] = v * scl;
        __syncthreads();
        float out = ((d & 1) == 0) ? (sh[d] * c - sh[d + 1] * sn)
                                   : (sh[d - 1] * sn + sh[d] * c);
        __nv_bfloat16 hh = __float2bfloat16(out);
        Qhi[off] = hh;
        Qlo[off] = __float2bfloat16(out - __bfloat162float(hh));
    }
    __syncthreads();
    {
        float v = K[off];
        float sq = v * v;
#pragma unroll
        for (int o = 16; o > 0; o >>= 1) sq += __shfl_xor_sync(0xffffffffu, sq, o);
        if ((d & 31) == 0) red[d >> 5] = sq;
        __syncthreads();
        float mean = (red[0] + red[1] + red[2] + red[3]) * (1.0f / HD);
        float scl = rsqrtf(mean + EPSF) * (txt ? gkc[d] : gk[d]);
        sh[d] = v * scl;
        __syncthreads();
        float out = ((d & 1) == 0) ? (sh[d] * c - sh[d + 1] * sn)
                                   : (sh[d - 1] * sn + sh[d] * c);
        __nv_bfloat16 hh = __float2bfloat16(out);
        Khi[off] = hh;
        Klo[off] = __float2bfloat16(out - __bfloat162float(hh));
    }
}

// ===========================================================================
// Flash attention via mma.sync, bf16 hi/lo 3-pass for QK^T and PV.
// BM=128 (8 warps x 16 rows), BN=32 per iter, HD=128.
// K/V hi/lo tiles in smem, 3-stage cp.async. Q frags register-resident.
// Output written pre-split to Xhi/Xlo (joint layout).
// ===========================================================================
#define FROW_B 272                           // smem row stride (128 bf16 + pad)
#define FK_HI 0
#define FK_LO (32 * FROW_B)                  // 8704
#define FV_HI (2 * 32 * FROW_B)              // 17408
#define FV_LO (3 * 32 * FROW_B)              // 26112
#define FSTAGE_B (4 * 32 * FROW_B)           // 34816
#define FNSTAGE 3
#define FLASH_SMEM_BYTES (FNSTAGE * FSTAGE_B)   // 104448 (Q staging: 2*128*272=69632 fits)
#define FITERS (SEQ / 32)                    // 48

__global__ void __launch_bounds__(256) flash_mma_kernel(
    const __nv_bfloat16* __restrict__ Qhi_g, const __nv_bfloat16* __restrict__ Qlo_g,
    const __nv_bfloat16* __restrict__ Khi_g, const __nv_bfloat16* __restrict__ Klo_g,
    const __nv_bfloat16* __restrict__ Vhi_g, const __nv_bfloat16* __restrict__ Vlo_g,
    __nv_bfloat16* __restrict__ Ohi, __nv_bfloat16* __restrict__ Olo)
{
    extern __shared__ __align__(128) char smem[];
    const uint32_t sbase = smem_u32(smem);
    const int tid = threadIdx.x;
    const int wq = tid >> 5, lane = tid & 31;
    const int q0 = blockIdx.x * 128;
    const int bh = blockIdx.y;
    const int b = bh / HEADS, h = bh % HEADS;
    const size_t hoff = (size_t)h * HD;

    // ---- stage Q tile (hi at 0, lo at 34816), extract to registers ----
    {
#pragma unroll
        for (int i = 0; i < 8; i++) {
            int f = tid + i * 256;               // 2048 chunks: r = f>>4, c16 = f&15
            int r = f >> 4, c = f & 15;
            uint32_t d = sbase + (uint32_t)r * FROW_B + c * 16;
            size_t so = (size_t)(b * SEQ + q0 + r) * DIM + hoff + c * 8;
            CPA16(d, (const void*)(Qhi_g + so));
            CPA16(d + 34816, (const void*)(Qlo_g + so));
        }
        CP_COMMIT();
        CP_WAIT(0);
        __syncthreads();
    }
    uint32_t qh[8][4], ql[8][4];
    {
        const uint32_t qrow = (uint32_t)(wq * 16 + (lane & 15));
        const uint32_t qc8  = (uint32_t)((lane >> 4) * 16);
#pragma unroll
        for (int ks = 0; ks < 8; ks++) {
            uint32_t ad = sbase + qrow * FROW_B + ks * 32 + qc8;
            LDM4(qh[ks], ad);
            LDM4(ql[ks], ad + 34816);
        }
    }
    __syncthreads();   // all warps done reading Q staging before K/V pipeline reuses smem

    // ---- K/V pipeline ----
#define FISSUE(kt) do { \
    const int k0 = (kt) * 32; \
    const uint32_t stb = sbase + ((kt) % FNSTAGE) * FSTAGE_B; \
    _Pragma("unroll") \
    for (int i = 0; i < 2; i++) { \
        int f = tid + i * 256; \
        int r = f >> 4, c = f & 15; \
        uint32_t d = stb + (uint32_t)r * FROW_B + c * 16; \
        size_t so = (size_t)(b * SEQ + k0 + r) * DIM + hoff + c * 8; \
        CPA16(d + FK_HI, (const void*)(Khi_g + so)); \
        CPA16(d + FK_LO, (const void*)(Klo_g + so)); \
        CPA16(d + FV_HI, (const void*)(Vhi_g + so)); \
        CPA16(d + FV_LO, (const void*)(Vlo_g + so)); \
    } \
    CP_COMMIT(); \
} while (0)

    float acc[16][4];
#pragma unroll
    for (int i = 0; i < 16; i++)
#pragma unroll
        for (int j = 0; j < 4; j++) acc[i][j] = 0.f;
    float m0 = -1e30f, m1 = -1e30f, l0 = 0.f, l1 = 0.f;

    const uint32_t krow = (uint32_t)(lane & 15);
    const uint32_t kc8  = (uint32_t)((lane >> 4) * 16);

    FISSUE(0); FISSUE(1);
    for (int kt = 0; kt < FITERS; kt++) {
        if (kt == FITERS - 1) { CP_WAIT(0); } else { CP_WAIT(1); }
        __syncthreads();
        if (kt + 2 < FITERS) FISSUE(kt + 2);
        const uint32_t stb = sbase + (kt % FNSTAGE) * FSTAGE_B;

        // ---- scores S = Q K^T (3-pass split) ----
        float s[4][4];
#pragma unroll
        for (int i = 0; i < 4; i++)
#pragma unroll
            for (int j = 0; j < 4; j++) s[i][j] = 0.f;
#pragma unroll
        for (int ks = 0; ks < 8; ks++) {
#pragma unroll
            for (int half = 0; half < 2; half++) {
                uint32_t kbh[4], kbl[4];
                uint32_t kd = stb + FK_HI + (half * 16 + krow) * FROW_B + ks * 32 + kc8;
                LDM4(kbh, kd);
                LDM4(kbl, kd + FK_LO);
                // nt = 2*half (b-frag {0,2}), nt = 2*half+1 (b-frag {1,3})
                MMA_BF16(s[2 * half + 0], qh[ks], kbh[0], kbh[2]);
                MMA_BF16(s[2 * half + 0], qh[ks], kbl[0], kbl[2]);
                MMA_BF16(s[2 * half + 0], ql[ks], kbh[0], kbh[2]);
                MMA_BF16(s[2 * half + 1], qh[ks], kbh[1], kbh[3]);
                MMA_BF16(s[2 * half + 1], qh[ks], kbl[1], kbl[3]);
                MMA_BF16(s[2 * half + 1], ql[ks], kbh[1], kbh[3]);
            }
        }
#pragma unroll
        for (int i = 0; i < 4; i++)
#pragma unroll
            for (int j = 0; j < 4; j++) s[i][j] *= SCALEF;

        // ---- online softmax (rows r = lane>>2 and r+8) ----
        float mx0 = fmaxf(fmaxf(s[0][0], s[0][1]), fmaxf(s[1][0], s[1][1]));
        mx0 = fmaxf(mx0, fmaxf(fmaxf(s[2][0], s[2][1]), fmaxf(s[3][0], s[3][1])));
        float mx1 = fmaxf(fmaxf(s[0][2], s[0][3]), fmaxf(s[1][2], s[1][3]));
        mx1 = fmaxf(mx1, fmaxf(fmaxf(s[2][2], s[2][3]), fmaxf(s[3][2], s[3][3])));
#pragma unroll
        for (int o = 1; o <= 2; o <<= 1) {
            mx0 = fmaxf(mx0, __shfl_xor_sync(0xffffffffu, mx0, o));
            mx1 = fmaxf(mx1, __shfl_xor_sync(0xffffffffu, mx1, o));
        }
        float mn0 = fmaxf(m0, mx0), mn1 = fmaxf(m1, mx1);
        float f0 = __expf(m0 - mn0), f1 = __expf(m1 - mn1);
        m0 = mn0; m1 = mn1;
        float rs0 = 0.f, rs1 = 0.f;
#pragma unroll
        for (int nt = 0; nt < 4; nt++) {
            s[nt][0] = __expf(s[nt][0] - mn0);
            s[nt][1] = __expf(s[nt][1] - mn0);
            s[nt][2] = __expf(s[nt][2] - mn1);
            s[nt][3] = __expf(s[nt][3] - mn1);
            rs0 += s[nt][0] + s[nt][1];
            rs1 += s[nt][2] + s[nt][3];
        }
#pragma unroll
        for (int o = 1; o <= 2; o <<= 1) {
            rs0 += __shfl_xor_sync(0xffffffffu, rs0, o);
            rs1 += __shfl_xor_sync(0xffffffffu, rs1, o);
        }
        l0 = l0 * f0 + rs0;
        l1 = l1 * f1 + rs1;
#pragma unroll
        for (int i = 0; i < 16; i++) {
            acc[i][0] *= f0; acc[i][1] *= f0;
            acc[i][2] *= f1; acc[i][3] *= f1;
        }

        // ---- P frags (hi/lo), then PV (3-pass) ----
        uint32_t ph[2][4], pl[2][4];
#pragma unroll
        for (int k2 = 0; k2 < 2; k2++) {
            ph[k2][0] = pack_split2(s[2 * k2][0],     s[2 * k2][1],     pl[k2][0]);
            ph[k2][1] = pack_split2(s[2 * k2][2],     s[2 * k2][3],     pl[k2][1]);
            ph[k2][2] = pack_split2(s[2 * k2 + 1][0], s[2 * k2 + 1][1], pl[k2][2]);
            ph[k2][3] = pack_split2(s[2 * k2 + 1][2], s[2 * k2 + 1][3], pl[k2][3]);
        }
#pragma unroll
        for (int ng = 0; ng < 8; ng++) {
#pragma unroll
            for (int k2 = 0; k2 < 2; k2++) {
                uint32_t vbh[4], vbl[4];
                uint32_t vd = stb + FV_HI + (k2 * 16 + krow) * FROW_B + ng * 32 + kc8;
                LDM4T(vbh, vd);
                LDM4T(vbl, vd + (FV_LO - FV_HI));
                MMA_BF16(acc[2 * ng + 0], ph[k2], vbh[0], vbh[1]);
                MMA_BF16(acc[2 * ng + 0], ph[k2], vbl[0], vbl[1]);
                MMA_BF16(acc[2 * ng + 0], pl[k2], vbh[0], vbh[1]);
                MMA_BF16(acc[2 * ng + 1], ph[k2], vbh[2], vbh[3]);
                MMA_BF16(acc[2 * ng + 1], ph[k2], vbl[2], vbl[3]);
                MMA_BF16(acc[2 * ng + 1], pl[k2], vbh[2], vbh[3]);
            }
        }
    }

    // ---- epilogue: normalize, split, store ----
    float inv0 = 1.0f / l0, inv1 = 1.0f / l1;
    const int r0g = b * SEQ + q0 + wq * 16 + (lane >> 2);
#pragma unroll
    for (int nt = 0; nt < 16; nt++) {
        int cc = (int)hoff + nt * 8 + ((lane & 3) << 1);
        uint32_t lo0, lo1;
        uint32_t hi0 = pack_split2(acc[nt][0] * inv0, acc[nt][1] * inv0, lo0);
        uint32_t hi1 = pack_split2(acc[nt][2] * inv1, acc[nt][3] * inv1, lo1);
        *(uint32_t*)(Ohi + (size_t)r0g * DIM + cc) = hi0;
        *(uint32_t*)(Olo + (size_t)r0g * DIM + cc) = lo0;
        *(uint32_t*)(Ohi + (size_t)(r0g + 8) * DIM + cc) = hi1;
        *(uint32_t*)(Olo + (size_t)(r0g + 8) * DIM + cc) = lo1;
    }
#undef FISSUE
}

// ---------------------------------------------------------------------------
extern "C" void kernel_launch(void* const* d_in, const int* in_sizes, int n_in,
                              void* d_out, int out_size)
{
    (void)in_sizes; (void)n_in; (void)out_size;
    const float* x     = (const float*)d_in[0];
    const float* ctx   = (const float*)d_in[1];
    const float* cosb  = (const float*)d_in[2];
    const float* sinb  = (const float*)d_in[3];
    const float* wptr[8] = {
        (const float*)d_in[4],   // 0: wq
        (const float*)d_in[6],   // 1: wk
        (const float*)d_in[8],   // 2: wv
        (const float*)d_in[10],  // 3: wqc
        (const float*)d_in[12],  // 4: wkc
        (const float*)d_in[14],  // 5: wvc
        (const float*)d_in[16],  // 6: w_out
        (const float*)d_in[18],  // 7: w_add_out
    };
    const float* bq    = (const float*)d_in[5];
    const float* bk    = (const float*)d_in[7];
    const float* bv    = (const float*)d_in[9];
    const float* bqc   = (const float*)d_in[11];
    const float* bkc   = (const float*)d_in[13];
    const float* bvc   = (const float*)d_in[15];
    const float* b_out = (const float*)d_in[17];
    const float* b_add = (const float*)d_in[19];
    const float* g_q   = (const float*)d_in[20];
    const float* g_k   = (const float*)d_in[21];
    const float* g_qc  = (const float*)d_in[22];
    const float* g_kc  = (const float*)d_in[23];
    float* out = (float*)d_out;

    float *QJ, *KJ, *VJ;
    __nv_bfloat16 *Whi, *Wlo, *Xhi, *Xlo, *Qhi, *Qlo, *Khi, *Klo, *Vhi, *Vlo;
    cudaGetSymbolAddress((void**)&QJ, g_QJ);
    cudaGetSymbolAddress((void**)&KJ, g_KJ);
    cudaGetSymbolAddress((void**)&VJ, g_VJ);
    cudaGetSymbolAddress((void**)&Whi, g_Whi);
    cudaGetSymbolAddress((void**)&Wlo, g_Wlo);
    cudaGetSymbolAddress((void**)&Xhi, g_Xhi);
    cudaGetSymbolAddress((void**)&Xlo, g_Xlo);
    cudaGetSymbolAddress((void**)&Qhi, g_Qhi);
    cudaGetSymbolAddress((void**)&Qlo, g_Qlo);
    cudaGetSymbolAddress((void**)&Khi, g_Khi);
    cudaGetSymbolAddress((void**)&Klo, g_Klo);
    cudaGetSymbolAddress((void**)&Vhi, g_Vhi);
    cudaGetSymbolAddress((void**)&Vlo, g_Vlo);

    cudaFuncSetAttribute(mma_gemm_kernel,
                         cudaFuncAttributeMaxDynamicSharedMemorySize, GEMM_SMEM_BYTES);
    cudaFuncSetAttribute(flash_mma_kernel,
                         cudaFuncAttributeMaxDynamicSharedMemorySize, FLASH_SMEM_BYTES);

    const int WN4 = DIM * DIM / 4;
    const size_t WSZ = (size_t)DIM * DIM;

    // preconvert weights
    for (int w = 0; w < 8; w++)
        split_kernel<<<(WN4 + 255) / 256, 256>>>(
            (const float4*)wptr[w], (uint2*)(Whi + w * WSZ), (uint2*)(Wlo + w * WSZ), WN4);

    // preconvert activations into joint layout
    split_act_kernel<<<(BB * S_TXT * (DIM / 4) + 255) / 256, 256>>>(
        (const float4*)ctx, (uint2*)Xhi, (uint2*)Xlo, S_TXT, 0);
    split_act_kernel<<<(BB * S_IMG * (DIM / 4) + 255) / 256, 256>>>(
        (const float4*)x, (uint2*)Xhi, (uint2*)Xlo, S_IMG, S_TXT);

    // QKV projections, merged z=3 (z: 0->Q, 1->K, 2->V)
    dim3 gImg3(DIM / 128, (BB * S_IMG) / 128, 3);
    dim3 gTxt3(DIM / 128, (BB * S_TXT) / 128, 3);
    mma_gemm_kernel<<<gImg3, 256, GEMM_SMEM_BYTES>>>(Xhi, Xlo, S_TXT, S_IMG,
        Whi, Wlo, 0, 1, 2, bq, bk, bv, QJ, KJ, VJ, SEQ, S_TXT);
    mma_gemm_kernel<<<gTxt3, 256, GEMM_SMEM_BYTES>>>(Xhi, Xlo, 0, S_TXT,
        Whi, Wlo, 3, 4, 5, bqc, bkc, bvc, QJ, KJ, VJ, SEQ, 0);

    // RMS+RoPE -> Q/K bf16 splits; V -> bf16 split
    rmsrope_kernel<<<BB * SEQ * HEADS, 128>>>(QJ, KJ, Qhi, Qlo, Khi, Klo,
                                              cosb, sinb, g_q, g_k, g_qc, g_kc);
    split_act_kernel<<<(BB * SEQ * (DIM / 4) + 255) / 256, 256>>>(
        (const float4*)VJ, (uint2*)Vhi, (uint2*)Vlo, SEQ, 0);

    // Flash attention (writes output splits into Xhi/Xlo)
    flash_mma_kernel<<<dim3(SEQ / 128, BB * HEADS), 256, FLASH_SMEM_BYTES>>>(
        Qhi, Qlo, Khi, Klo, Vhi, Vlo, Xhi, Xlo);

    // output projections
    dim3 gTxt(DIM / 128, (BB * S_TXT) / 128, 1);
    dim3 gImg(DIM / 128, (BB * S_IMG) / 128, 1);
    mma_gemm_kernel<<<gTxt, 256, GEMM_SMEM_BYTES>>>(Xhi, Xlo, 0, S_TXT,
        Whi, Wlo, 7, 7, 7, b_add, b_add, b_add, out, out, out, S_TXT, 0);
    mma_gemm_kernel<<<gImg, 256, GEMM_SMEM_BYTES>>>(Xhi, Xlo, S_TXT, S_IMG,
        Whi, Wlo, 6, 6, 6, b_out, b_out, b_out,
        out + (size_t)BB * S_TXT * DIM, out + (size_t)BB * S_TXT * DIM,
        out + (size_t)BB * S_TXT * DIM, S_IMG, 0);
}

// round 7
// speedup vs baseline: 4.8685x; 1.5264x over previous
#include <cuda_runtime.h>
#include <cuda_fp16.h>
#include <cstdint>
#include <math.h>

#define BB 2
#define S_IMG 1024
#define S_TXT 512
#define SEQ 1536
#define DIM 3072
#define HEADS 24
#define HD 128
#define EPSF 1e-6f
#define SCALEF 0.08838834764831845f

// Scratch (device globals -- no allocation allowed)
__device__ float g_QJ[BB * SEQ * DIM];
__device__ float g_KJ[BB * SEQ * DIM];
__device__ float g_VJ[BB * SEQ * DIM];
__device__ __half g_Whi[8 * DIM * DIM];
__device__ __half g_Wlo[8 * DIM * DIM];
__device__ __half g_Xhi[BB * SEQ * DIM];
__device__ __half g_Qhi[BB * SEQ * DIM];
__device__ __half g_Qlo[BB * SEQ * DIM];
__device__ __half g_Khi[BB * SEQ * DIM];
__device__ __half g_Klo[BB * SEQ * DIM];
__device__ __half g_Vhi[BB * SEQ * DIM];
__device__ __half g_Vlo[BB * SEQ * DIM];

// ===========================================================================
// helpers
// ===========================================================================
__device__ __forceinline__ uint32_t smem_u32(const void* p) {
    uint32_t a;
    asm("{ .reg .u64 t; cvta.to.shared.u64 t, %1; cvt.u32.u64 %0, t; }"
        : "=r"(a) : "l"(p));
    return a;
}
#define LDM4(r, a) \
    asm volatile("ldmatrix.sync.aligned.m8n8.x4.shared.b16 {%0,%1,%2,%3}, [%4];" \
        : "=r"((r)[0]), "=r"((r)[1]), "=r"((r)[2]), "=r"((r)[3]) : "r"(a))
#define LDM4T(r, a) \
    asm volatile("ldmatrix.sync.aligned.m8n8.x4.trans.shared.b16 {%0,%1,%2,%3}, [%4];" \
        : "=r"((r)[0]), "=r"((r)[1]), "=r"((r)[2]), "=r"((r)[3]) : "r"(a))
#define MMA_F16(d, a, b0, b1) \
    asm volatile("mma.sync.aligned.m16n8k16.row.col.f32.f16.f16.f32 " \
        "{%0,%1,%2,%3}, {%4,%5,%6,%7}, {%8,%9}, {%0,%1,%2,%3};" \
        : "+f"((d)[0]), "+f"((d)[1]), "+f"((d)[2]), "+f"((d)[3]) \
        : "r"((a)[0]), "r"((a)[1]), "r"((a)[2]), "r"((a)[3]), "r"(b0), "r"(b1))
#define CPA16(dst, src) \
    asm volatile("cp.async.cg.shared.global [%0], [%1], 16;" :: "r"(dst), "l"(src))
#define CP_COMMIT() asm volatile("cp.async.commit_group;" ::: "memory")
#define CP_WAIT(n)  asm volatile("cp.async.wait_group %0;" :: "n"(n) : "memory")

__device__ __forceinline__ uint32_t pack_h2(float a, float b) {
    __half2 h = __floats2half2_rn(a, b);
    return *(uint32_t*)&h;
}
__device__ __forceinline__ void split_f16x4(float4 v, uint2& ph, uint2& pl) {
    __half hx = __float2half_rn(v.x), hy = __float2half_rn(v.y);
    __half hz = __float2half_rn(v.z), hw = __float2half_rn(v.w);
    ph.x = ((uint32_t)__half_as_ushort(hy) << 16) | __half_as_ushort(hx);
    ph.y = ((uint32_t)__half_as_ushort(hw) << 16) | __half_as_ushort(hz);
    __half lx = __float2half_rn(v.x - __half2float(hx));
    __half ly = __float2half_rn(v.y - __half2float(hy));
    __half lz = __float2half_rn(v.z - __half2float(hz));
    __half lw = __float2half_rn(v.w - __half2float(hw));
    pl.x = ((uint32_t)__half_as_ushort(ly) << 16) | __half_as_ushort(lx);
    pl.y = ((uint32_t)__half_as_ushort(lw) << 16) | __half_as_ushort(lz);
}

// ---------------------------------------------------------------------------
// conversion kernels
// ---------------------------------------------------------------------------
__global__ void __launch_bounds__(256) split_w_kernel(
    const float4* __restrict__ src, uint2* __restrict__ hi, uint2* __restrict__ lo, int n4)
{
    int i = blockIdx.x * 256 + threadIdx.x;
    if (i < n4) {
        uint2 ph, pl;
        split_f16x4(src[i], ph, pl);
        hi[i] = ph; lo[i] = pl;
    }
}

// fp32 [BB][rpb][DIM] -> fp16 hi only, joint rows (b*SEQ + dst_off + s)
__global__ void __launch_bounds__(256) conv_hi_kernel(
    const float4* __restrict__ src, uint2* __restrict__ hi, int rpb, int dst_off)
{
    int i = blockIdx.x * 256 + threadIdx.x;
    int n4 = BB * rpb * (DIM / 4);
    if (i < n4) {
        int q = i % (DIM / 4);
        int row = i / (DIM / 4);
        int b = row / rpb, s = row % rpb;
        float4 v = src[i];
        uint2 ph;
        ph.x = pack_h2(v.x, v.y);
        ph.y = pack_h2(v.z, v.w);
        hi[(b * SEQ + dst_off + s) * (DIM / 4) + q] = ph;
    }
}

// fp32 joint -> fp16 hi/lo joint (for V)
__global__ void __launch_bounds__(256) split_hl_kernel(
    const float4* __restrict__ src, uint2* __restrict__ hi, uint2* __restrict__ lo, int n4)
{
    int i = blockIdx.x * 256 + threadIdx.x;
    if (i < n4) {
        uint2 ph, pl;
        split_f16x4(src[i], ph, pl);
        hi[i] = ph; lo[i] = pl;
    }
}

// ===========================================================================
// fp16 2-pass GEMM: C = A @ W + bias;  A hi-only fp16, W split hi/lo fp16.
// D = Ah*Wh + Ah*Wl (fp32 accum). Tile 128x128, KC=32, 4-stage cp.async.
// Warp layout 2M x 4N (each warp 64 rows x 32 cols) to balance smem traffic.
// ===========================================================================
#define KC 32
#define CHUNKS (DIM / KC)                  // 96
#define A_ST2 80                            // 64B data + 16 pad
#define B_ST2 272                           // 256B data + 16 pad
#define A_TILE_B (128 * A_ST2)              // 10240 (hi only)
#define B_TILE_B (32 * B_ST2)               // 8704
#define OFF_BHI A_TILE_B                    // 10240
#define OFF_BLO (A_TILE_B + B_TILE_B)       // 18944
#define STAGE_B (A_TILE_B + 2 * B_TILE_B)   // 27648
#define NSTAGE 4
#define GEMM_SMEM_BYTES (NSTAGE * STAGE_B)  // 110592

__global__ void __launch_bounds__(256) mma_gemm_kernel(
    const __half* __restrict__ Ahi_g, int a_off, int rpb,
    const __half* __restrict__ Whi_base, const __half* __restrict__ Wlo_base,
    int w0, int w1, int w2,
    const float* bias0, const float* bias1, const float* bias2,
    float* C0, float* C1, float* C2,
    int c_seq, int c_off)
{
    extern __shared__ __align__(128) char smem[];
    const uint32_t sbase = smem_u32(smem);
    const int tid = threadIdx.x;
    const int wid = tid >> 5, lane = tid & 31;
    const int warp_m = wid >> 2;           // 2 groups of 64 rows
    const int warp_n = wid & 3;            // 4 groups of 32 cols
    const int z = blockIdx.z;

    const int widx = (z == 0) ? w0 : ((z == 1) ? w1 : w2);
    const float* bias = (z == 0) ? bias0 : ((z == 1) ? bias1 : bias2);
    float* C_base = (z == 0) ? C0 : ((z == 1) ? C1 : C2);
    const __half* Whi = Whi_base + (size_t)widx * DIM * DIM;
    const __half* Wlo = Wlo_base + (size_t)widx * DIM * DIM;

    const int row0 = blockIdx.y * 128;
    const int col0 = blockIdx.x * 128;
    const int b  = row0 / rpb;
    const int s0 = row0 % rpb;
    const __half* Ahi = Ahi_g + (size_t)(b * SEQ + a_off + s0) * DIM;
    float* C = C_base + (size_t)(b * c_seq + c_off + s0) * DIM;

#define ISSUE(c) do { \
    const int k0 = (c) * KC; \
    const uint32_t stb = sbase + ((c) % NSTAGE) * STAGE_B; \
    _Pragma("unroll") \
    for (int i = 0; i < 2; i++) { \
        int f = tid + i * 256; \
        uint32_t d = stb + (uint32_t)(f >> 2) * A_ST2 + (f & 3) * 16; \
        size_t so = (size_t)(f >> 2) * DIM + k0 + ((f & 3) << 3); \
        CPA16(d, (const void*)(Ahi + so)); \
        uint32_t db = stb + OFF_BHI + (uint32_t)(f >> 4) * B_ST2 + (f & 15) * 16; \
        size_t sb2 = (size_t)(k0 + (f >> 4)) * DIM + col0 + ((f & 15) << 3); \
        CPA16(db, (const void*)(Whi + sb2)); \
        CPA16(db + B_TILE_B, (const void*)(Wlo + sb2)); \
    } \
    CP_COMMIT(); \
} while (0)

    float acc[4][4][4];
#pragma unroll
    for (int i = 0; i < 4; i++)
#pragma unroll
        for (int j = 0; j < 4; j++)
#pragma unroll
            for (int k = 0; k < 4; k++) acc[i][j][k] = 0.f;

    const uint32_t a_row = (uint32_t)(warp_m * 64 + (lane & 15));
    const uint32_t a_sel = (uint32_t)((lane >> 4) * 16);
    const uint32_t b_row = (uint32_t)(lane & 15);
    const uint32_t b_sel = (uint32_t)(warp_n * 64 + ((lane >> 4) * 16));

#define COMPUTE(sidx) do { \
    const uint32_t sb = sbase + (sidx) * STAGE_B; \
    _Pragma("unroll") \
    for (int ks = 0; ks < 2; ks++) { \
        uint32_t ah[4][4]; \
        _Pragma("unroll") \
        for (int mt = 0; mt < 4; mt++) { \
            uint32_t ad = sb + (a_row + mt * 16) * A_ST2 + ks * 32 + a_sel; \
            LDM4(ah[mt], ad); \
        } \
        _Pragma("unroll") \
        for (int ng = 0; ng < 2; ng++) { \
            uint32_t bh[4], bl[4]; \
            uint32_t bd = sb + OFF_BHI + (ks * 16 + b_row) * B_ST2 + b_sel + ng * 32; \
            LDM4T(bh, bd); \
            LDM4T(bl, bd + B_TILE_B); \
            _Pragma("unroll") \
            for (int mt = 0; mt < 4; mt++) { \
                MMA_F16(acc[mt][ng * 2 + 0], ah[mt], bh[0], bh[1]); \
                MMA_F16(acc[mt][ng * 2 + 0], ah[mt], bl[0], bl[1]); \
                MMA_F16(acc[mt][ng * 2 + 1], ah[mt], bh[2], bh[3]); \
                MMA_F16(acc[mt][ng * 2 + 1], ah[mt], bl[2], bl[3]); \
            } \
        } \
    } \
} while (0)

    ISSUE(0); ISSUE(1); ISSUE(2);
    for (int c = 0; c < CHUNKS; c++) {
        if (c < CHUNKS - 2) { CP_WAIT(2); }
        else if (c == CHUNKS - 2) { CP_WAIT(1); }
        else { CP_WAIT(0); }
        __syncthreads();
        if (c + 3 < CHUNKS) ISSUE(c + 3);
        COMPUTE(c % NSTAGE);
    }

    const int m_base = warp_m * 64;
    const int n_base = col0 + warp_n * 32;
#pragma unroll
    for (int mt = 0; mt < 4; mt++) {
#pragma unroll
        for (int nt = 0; nt < 4; nt++) {
            int r  = m_base + mt * 16 + (lane >> 2);
            int cc = n_base + nt * 8 + ((lane & 3) << 1);
            float b0 = bias[cc], b1 = bias[cc + 1];
            float2 v0 = make_float2(acc[mt][nt][0] + b0, acc[mt][nt][1] + b1);
            float2 v1 = make_float2(acc[mt][nt][2] + b0, acc[mt][nt][3] + b1);
            *(float2*)(C + (size_t)r * DIM + cc) = v0;
            *(float2*)(C + (size_t)(r + 8) * DIM + cc) = v1;
        }
    }
#undef ISSUE
#undef COMPUTE
}

// ---------------------------------------------------------------------------
// Fused RMS-norm + RoPE; reads fp32 Q/K, writes fp16 hi/lo splits.
// ---------------------------------------------------------------------------
__global__ void __launch_bounds__(128) rmsrope_kernel(
    const float* __restrict__ Q, const float* __restrict__ K,
    __half* __restrict__ Qhi, __half* __restrict__ Qlo,
    __half* __restrict__ Khi, __half* __restrict__ Klo,
    const float* __restrict__ cosb, const float* __restrict__ sinb,
    const float* __restrict__ gq, const float* __restrict__ gk,
    const float* __restrict__ gqc, const float* __restrict__ gkc)
{
    const int idx = blockIdx.x;
    const int h = idx % HEADS;
    const int s = (idx / HEADS) % SEQ;
    const int b = idx / (HEADS * SEQ);
    const int d = threadIdx.x;
    const size_t off = ((size_t)(b * SEQ + s)) * DIM + h * HD + d;
    __shared__ float sh[HD];
    __shared__ float red[4];
    const float c  = cosb[s * (HD / 2) + (d >> 1)];
    const float sn = sinb[s * (HD / 2) + (d >> 1)];
    const bool txt = (s < S_TXT);

    {
        float v = Q[off];
        float sq = v * v;
#pragma unroll
        for (int o = 16; o > 0; o >>= 1) sq += __shfl_xor_sync(0xffffffffu, sq, o);
        if ((d & 31) == 0) red[d >> 5] = sq;
        __syncthreads();
        float mean = (red[0] + red[1] + red[2] + red[3]) * (1.0f / HD);
        float scl = rsqrtf(mean + EPSF) * (txt ? gqc[d] : gq[d]);
        sh[d] = v * scl;
        __syncthreads();
        float out = ((d & 1) == 0) ? (sh[d] * c - sh[d + 1] * sn)
                                   : (sh[d - 1] * sn + sh[d] * c);
        __half hh = __float2half_rn(out);
        Qhi[off] = hh;
        Qlo[off] = __float2half_rn(out - __half2float(hh));
    }
    __syncthreads();
    {
        float v = K[off];
        float sq = v * v;
#pragma unroll
        for (int o = 16; o > 0; o >>= 1) sq += __shfl_xor_sync(0xffffffffu, sq, o);
        if ((d & 31) == 0) red[d >> 5] = sq;
        __syncthreads();
        float mean = (red[0] + red[1] + red[2] + red[3]) * (1.0f / HD);
        float scl = rsqrtf(mean + EPSF) * (txt ? gkc[d] : gk[d]);
        sh[d] = v * scl;
        __syncthreads();
        float out = ((d & 1) == 0) ? (sh[d] * c - sh[d + 1] * sn)
                                   : (sh[d - 1] * sn + sh[d] * c);
        __half hh = __float2half_rn(out);
        Khi[off] = hh;
        Klo[off] = __float2half_rn(out - __half2float(hh));
    }
}

// ===========================================================================
// Flash attention via mma.sync fp16. QK^T 3-pass (hi/lo), PV 2-pass (P hi).
// BM=128 (8 warps x 16 rows), BN=32, HD=128. Output written hi-only to Xhi.
// ===========================================================================
#define FROW_B 272
#define FK_HI 0
#define FK_LO (32 * FROW_B)
#define FV_HI (2 * 32 * FROW_B)
#define FV_LO (3 * 32 * FROW_B)
#define FSTAGE_B (4 * 32 * FROW_B)          // 34816
#define FNSTAGE 3
#define FLASH_SMEM_BYTES (FNSTAGE * FSTAGE_B)
#define FITERS (SEQ / 32)

__global__ void __launch_bounds__(256) flash_mma_kernel(
    const __half* __restrict__ Qhi_g, const __half* __restrict__ Qlo_g,
    const __half* __restrict__ Khi_g, const __half* __restrict__ Klo_g,
    const __half* __restrict__ Vhi_g, const __half* __restrict__ Vlo_g,
    __half* __restrict__ Ohi)
{
    extern __shared__ __align__(128) char smem[];
    const uint32_t sbase = smem_u32(smem);
    const int tid = threadIdx.x;
    const int wq = tid >> 5, lane = tid & 31;
    const int q0 = blockIdx.x * 128;
    const int bh = blockIdx.y;
    const int b = bh / HEADS, h = bh % HEADS;
    const size_t hoff = (size_t)h * HD;

    // stage Q tile (hi at 0, lo at +34816)
    {
#pragma unroll
        for (int i = 0; i < 8; i++) {
            int f = tid + i * 256;
            int r = f >> 4, c = f & 15;
            uint32_t d = sbase + (uint32_t)r * FROW_B + c * 16;
            size_t so = (size_t)(b * SEQ + q0 + r) * DIM + hoff + c * 8;
            CPA16(d, (const void*)(Qhi_g + so));
            CPA16(d + 34816, (const void*)(Qlo_g + so));
        }
        CP_COMMIT();
        CP_WAIT(0);
        __syncthreads();
    }
    uint32_t qh[8][4], ql[8][4];
    {
        const uint32_t qrow = (uint32_t)(wq * 16 + (lane & 15));
        const uint32_t qc8  = (uint32_t)((lane >> 4) * 16);
#pragma unroll
        for (int ks = 0; ks < 8; ks++) {
            uint32_t ad = sbase + qrow * FROW_B + ks * 32 + qc8;
            LDM4(qh[ks], ad);
            LDM4(ql[ks], ad + 34816);
        }
    }
    __syncthreads();

#define FISSUE(kt) do { \
    const int k0 = (kt) * 32; \
    const uint32_t stb = sbase + ((kt) % FNSTAGE) * FSTAGE_B; \
    _Pragma("unroll") \
    for (int i = 0; i < 2; i++) { \
        int f = tid + i * 256; \
        int r = f >> 4, c = f & 15; \
        uint32_t d = stb + (uint32_t)r * FROW_B + c * 16; \
        size_t so = (size_t)(b * SEQ + k0 + r) * DIM + hoff + c * 8; \
        CPA16(d + FK_HI, (const void*)(Khi_g + so)); \
        CPA16(d + FK_LO, (const void*)(Klo_g + so)); \
        CPA16(d + FV_HI, (const void*)(Vhi_g + so)); \
        CPA16(d + FV_LO, (const void*)(Vlo_g + so)); \
    } \
    CP_COMMIT(); \
} while (0)

    float acc[16][4];
#pragma unroll
    for (int i = 0; i < 16; i++)
#pragma unroll
        for (int j = 0; j < 4; j++) acc[i][j] = 0.f;
    float m0 = -1e30f, m1 = -1e30f, l0 = 0.f, l1 = 0.f;

    const uint32_t krow = (uint32_t)(lane & 15);
    const uint32_t kc8  = (uint32_t)((lane >> 4) * 16);

    FISSUE(0); FISSUE(1);
    for (int kt = 0; kt < FITERS; kt++) {
        if (kt == FITERS - 1) { CP_WAIT(0); } else { CP_WAIT(1); }
        __syncthreads();
        if (kt + 2 < FITERS) FISSUE(kt + 2);
        const uint32_t stb = sbase + (kt % FNSTAGE) * FSTAGE_B;

        // scores: 3-pass (QhKh + QhKl + QlKh)
        float s[4][4];
#pragma unroll
        for (int i = 0; i < 4; i++)
#pragma unroll
            for (int j = 0; j < 4; j++) s[i][j] = 0.f;
#pragma unroll
        for (int ks = 0; ks < 8; ks++) {
#pragma unroll
            for (int half = 0; half < 2; half++) {
                uint32_t kbh[4], kbl[4];
                uint32_t kd = stb + FK_HI + (half * 16 + krow) * FROW_B + ks * 32 + kc8;
                LDM4(kbh, kd);
                LDM4(kbl, kd + FK_LO);
                MMA_F16(s[2 * half + 0], qh[ks], kbh[0], kbh[2]);
                MMA_F16(s[2 * half + 0], qh[ks], kbl[0], kbl[2]);
                MMA_F16(s[2 * half + 0], ql[ks], kbh[0], kbh[2]);
                MMA_F16(s[2 * half + 1], qh[ks], kbh[1], kbh[3]);
                MMA_F16(s[2 * half + 1], qh[ks], kbl[1], kbl[3]);
                MMA_F16(s[2 * half + 1], ql[ks], kbh[1], kbh[3]);
            }
        }
#pragma unroll
        for (int i = 0; i < 4; i++)
#pragma unroll
            for (int j = 0; j < 4; j++) s[i][j] *= SCALEF;

        // online softmax
        float mx0 = fmaxf(fmaxf(s[0][0], s[0][1]), fmaxf(s[1][0], s[1][1]));
        mx0 = fmaxf(mx0, fmaxf(fmaxf(s[2][0], s[2][1]), fmaxf(s[3][0], s[3][1])));
        float mx1 = fmaxf(fmaxf(s[0][2], s[0][3]), fmaxf(s[1][2], s[1][3]));
        mx1 = fmaxf(mx1, fmaxf(fmaxf(s[2][2], s[2][3]), fmaxf(s[3][2], s[3][3])));
#pragma unroll
        for (int o = 1; o <= 2; o <<= 1) {
            mx0 = fmaxf(mx0, __shfl_xor_sync(0xffffffffu, mx0, o));
            mx1 = fmaxf(mx1, __shfl_xor_sync(0xffffffffu, mx1, o));
        }
        float mn0 = fmaxf(m0, mx0), mn1 = fmaxf(m1, mx1);
        float f0 = __expf(m0 - mn0), f1 = __expf(m1 - mn1);
        m0 = mn0; m1 = mn1;
        float rs0 = 0.f, rs1 = 0.f;
#pragma unroll
        for (int nt = 0; nt < 4; nt++) {
            s[nt][0] = __expf(s[nt][0] - mn0);
            s[nt][1] = __expf(s[nt][1] - mn0);
            s[nt][2] = __expf(s[nt][2] - mn1);
            s[nt][3] = __expf(s[nt][3] - mn1);
            rs0 += s[nt][0] + s[nt][1];
            rs1 += s[nt][2] + s[nt][3];
        }
#pragma unroll
        for (int o = 1; o <= 2; o <<= 1) {
            rs0 += __shfl_xor_sync(0xffffffffu, rs0, o);
            rs1 += __shfl_xor_sync(0xffffffffu, rs1, o);
        }
        l0 = l0 * f0 + rs0;
        l1 = l1 * f1 + rs1;
#pragma unroll
        for (int i = 0; i < 16; i++) {
            acc[i][0] *= f0; acc[i][1] *= f0;
            acc[i][2] *= f1; acc[i][3] *= f1;
        }

        // P hi frags, PV 2-pass (PhVh + PhVl)
        uint32_t ph[2][4];
#pragma unroll
        for (int k2 = 0; k2 < 2; k2++) {
            ph[k2][0] = pack_h2(s[2 * k2][0],     s[2 * k2][1]);
            ph[k2][1] = pack_h2(s[2 * k2][2],     s[2 * k2][3]);
            ph[k2][2] = pack_h2(s[2 * k2 + 1][0], s[2 * k2 + 1][1]);
            ph[k2][3] = pack_h2(s[2 * k2 + 1][2], s[2 * k2 + 1][3]);
        }
#pragma unroll
        for (int ng = 0; ng < 8; ng++) {
#pragma unroll
            for (int k2 = 0; k2 < 2; k2++) {
                uint32_t vbh[4], vbl[4];
                uint32_t vd = stb + FV_HI + (k2 * 16 + krow) * FROW_B + ng * 32 + kc8;
                LDM4T(vbh, vd);
                LDM4T(vbl, vd + (FV_LO - FV_HI));
                MMA_F16(acc[2 * ng + 0], ph[k2], vbh[0], vbh[1]);
                MMA_F16(acc[2 * ng + 0], ph[k2], vbl[0], vbl[1]);
                MMA_F16(acc[2 * ng + 1], ph[k2], vbh[2], vbh[3]);
                MMA_F16(acc[2 * ng + 1], ph[k2], vbl[2], vbl[3]);
            }
        }
    }

    // epilogue: normalize, store hi only
    float inv0 = 1.0f / l0, inv1 = 1.0f / l1;
    const int r0g = b * SEQ + q0 + wq * 16 + (lane >> 2);
#pragma unroll
    for (int nt = 0; nt < 16; nt++) {
        int cc = (int)hoff + nt * 8 + ((lane & 3) << 1);
        *(uint32_t*)(Ohi + (size_t)r0g * DIM + cc) =
            pack_h2(acc[nt][0] * inv0, acc[nt][1] * inv0);
        *(uint32_t*)(Ohi + (size_t)(r0g + 8) * DIM + cc) =
            pack_h2(acc[nt][2] * inv1, acc[nt][3] * inv1);
    }
#undef FISSUE
}

// ---------------------------------------------------------------------------
extern "C" void kernel_launch(void* const* d_in, const int* in_sizes, int n_in,
                              void* d_out, int out_size)
{
    (void)in_sizes; (void)n_in; (void)out_size;
    const float* x     = (const float*)d_in[0];
    const float* ctx   = (const float*)d_in[1];
    const float* cosb  = (const float*)d_in[2];
    const float* sinb  = (const float*)d_in[3];
    const float* wptr[8] = {
        (const float*)d_in[4],   // 0: wq
        (const float*)d_in[6],   // 1: wk
        (const float*)d_in[8],   // 2: wv
        (const float*)d_in[10],  // 3: wqc
        (const float*)d_in[12],  // 4: wkc
        (const float*)d_in[14],  // 5: wvc
        (const float*)d_in[16],  // 6: w_out
        (const float*)d_in[18],  // 7: w_add_out
    };
    const float* bq    = (const float*)d_in[5];
    const float* bk    = (const float*)d_in[7];
    const float* bv    = (const float*)d_in[9];
    const float* bqc   = (const float*)d_in[11];
    const float* bkc   = (const float*)d_in[13];
    const float* bvc   = (const float*)d_in[15];
    const float* b_out = (const float*)d_in[17];
    const float* b_add = (const float*)d_in[19];
    const float* g_q   = (const float*)d_in[20];
    const float* g_k   = (const float*)d_in[21];
    const float* g_qc  = (const float*)d_in[22];
    const float* g_kc  = (const float*)d_in[23];
    float* out = (float*)d_out;

    float *QJ, *KJ, *VJ;
    __half *Whi, *Wlo, *Xhi, *Qhi, *Qlo, *Khi, *Klo, *Vhi, *Vlo;
    cudaGetSymbolAddress((void**)&QJ, g_QJ);
    cudaGetSymbolAddress((void**)&KJ, g_KJ);
    cudaGetSymbolAddress((void**)&VJ, g_VJ);
    cudaGetSymbolAddress((void**)&Whi, g_Whi);
    cudaGetSymbolAddress((void**)&Wlo, g_Wlo);
    cudaGetSymbolAddress((void**)&Xhi, g_Xhi);
    cudaGetSymbolAddress((void**)&Qhi, g_Qhi);
    cudaGetSymbolAddress((void**)&Qlo, g_Qlo);
    cudaGetSymbolAddress((void**)&Khi, g_Khi);
    cudaGetSymbolAddress((void**)&Klo, g_Klo);
    cudaGetSymbolAddress((void**)&Vhi, g_Vhi);
    cudaGetSymbolAddress((void**)&Vlo, g_Vlo);

    cudaFuncSetAttribute(mma_gemm_kernel,
                         cudaFuncAttributeMaxDynamicSharedMemorySize, GEMM_SMEM_BYTES);
    cudaFuncSetAttribute(flash_mma_kernel,
                         cudaFuncAttributeMaxDynamicSharedMemorySize, FLASH_SMEM_BYTES);

    const int WN4 = DIM * DIM / 4;
    const size_t WSZ = (size_t)DIM * DIM;

    // preconvert weights (fp16 hi/lo)
    for (int w = 0; w < 8; w++)
        split_w_kernel<<<(WN4 + 255) / 256, 256>>>(
            (const float4*)wptr[w], (uint2*)(Whi + w * WSZ), (uint2*)(Wlo + w * WSZ), WN4);

    // preconvert activations (fp16 hi only) into joint layout
    conv_hi_kernel<<<(BB * S_TXT * (DIM / 4) + 255) / 256, 256>>>(
        (const float4*)ctx, (uint2*)Xhi, S_TXT, 0);
    conv_hi_kernel<<<(BB * S_IMG * (DIM / 4) + 255) / 256, 256>>>(
        (const float4*)x, (uint2*)Xhi, S_IMG, S_TXT);

    // QKV projections, merged z=3
    dim3 gImg3(DIM / 128, (BB * S_IMG) / 128, 3);
    dim3 gTxt3(DIM / 128, (BB * S_TXT) / 128, 3);
    mma_gemm_kernel<<<gImg3, 256, GEMM_SMEM_BYTES>>>(Xhi, S_TXT, S_IMG,
        Whi, Wlo, 0, 1, 2, bq, bk, bv, QJ, KJ, VJ, SEQ, S_TXT);
    mma_gemm_kernel<<<gTxt3, 256, GEMM_SMEM_BYTES>>>(Xhi, 0, S_TXT,
        Whi, Wlo, 3, 4, 5, bqc, bkc, bvc, QJ, KJ, VJ, SEQ, 0);

    // RMS+RoPE -> Q/K fp16 splits; V -> fp16 split
    rmsrope_kernel<<<BB * SEQ * HEADS, 128>>>(QJ, KJ, Qhi, Qlo, Khi, Klo,
                                              cosb, sinb, g_q, g_k, g_qc, g_kc);
    split_hl_kernel<<<(BB * SEQ * (DIM / 4) + 255) / 256, 256>>>(
        (const float4*)VJ, (uint2*)Vhi, (uint2*)Vlo, BB * SEQ * (DIM / 4));

    // Flash attention (writes fp16 hi output into Xhi)
    flash_mma_kernel<<<dim3(SEQ / 128, BB * HEADS), 256, FLASH_SMEM_BYTES>>>(
        Qhi, Qlo, Khi, Klo, Vhi, Vlo, Xhi);

    // output projections
    dim3 gTxt(DIM / 128, (BB * S_TXT) / 128, 1);
    dim3 gImg(DIM / 128, (BB * S_IMG) / 128, 1);
    mma_gemm_kernel<<<gTxt, 256, GEMM_SMEM_BYTES>>>(Xhi, 0, S_TXT,
        Whi, Wlo, 7, 7, 7, b_add, b_add, b_add, out, out, out, S_TXT, 0);
    mma_gemm_kernel<<<gImg, 256, GEMM_SMEM_BYTES>>>(Xhi, S_TXT, S_IMG,
        Whi, Wlo, 6, 6, 6, b_out, b_out, b_out,
        out + (size_t)BB * S_TXT * DIM, out + (size_t)BB * S_TXT * DIM,
        out + (size_t)BB * S_TXT * DIM, S_IMG, 0);
}